// round 10
// baseline (speedup 1.0000x reference)
#include <cuda_runtime.h>
#include <cuda_bf16.h>

#define N_NODES 100000
#define N_EDGES 1600000
#define D_IN    64
#define D_H     128
#define D_M     256
#define D_OUT   40
#define NB_SCAN 391   // ceil(N_NODES/256)
#define KP128 136
#define KP256 264

// ---------------- device-global scratch --------------------------------------
__device__ int g_cnt_i[N_NODES];
__device__ int g_rs  [N_NODES];
__device__ int g_wr  [N_NODES];
__device__ int g_bsum[512];
__device__ int g_adj [N_EDGES];
__device__ __align__(16) __nv_bfloat16 g_fhi [(size_t)N_NODES * D_IN];
__device__ __align__(16) __nv_bfloat16 g_flo [(size_t)N_NODES * D_IN];
__device__ __align__(16) __nv_bfloat16 g_h1hi[(size_t)N_NODES * D_H];
__device__ __align__(16) __nv_bfloat16 g_h1lo[(size_t)N_NODES * D_H];
// pre-split weights, padded to smem tile layout (n-major, stride KP*)
__device__ __align__(16) __nv_bfloat16 g_w1hi[128 * KP128], g_w1lo[128 * KP128];
__device__ __align__(16) __nv_bfloat16 g_w2hi[128 * KP256], g_w2lo[128 * KP256];
__device__ __align__(16) __nv_bfloat16 g_m1hi[256 * KP128], g_m1lo[256 * KP128];
__device__ __align__(16) __nv_bfloat16 g_m2hi[ 40 * KP256], g_m2lo[ 40 * KP256];

// ---------------- helpers ----------------------------------------------------
__device__ __forceinline__ float sigmoidf_(float x) {
    return 1.0f / (1.0f + __expf(-x));
}
__device__ __forceinline__ void split2(float x, __nv_bfloat16& hi, __nv_bfloat16& lo) {
    hi = __float2bfloat16(x);
    lo = __float2bfloat16(x - __bfloat162float(hi));
}
__device__ __forceinline__ unsigned pack_bf2(__nv_bfloat16 a, __nv_bfloat16 b) {
    return (unsigned)__bfloat16_as_ushort(a) | ((unsigned)__bfloat16_as_ushort(b) << 16);
}
__device__ __forceinline__ float2 bf2f2(unsigned u) {
    __nv_bfloat162 b = *(__nv_bfloat162*)&u;
    return __bfloat1622float2(b);
}

__device__ __forceinline__ void mma_bf16(float c[4], const unsigned a[4],
                                         unsigned b0, unsigned b1) {
    asm volatile("mma.sync.aligned.m16n8k16.row.col.f32.bf16.bf16.f32 "
                 "{%0,%1,%2,%3}, {%4,%5,%6,%7}, {%8,%9}, {%0,%1,%2,%3};"
                 : "+f"(c[0]), "+f"(c[1]), "+f"(c[2]), "+f"(c[3])
                 : "r"(a[0]), "r"(a[1]), "r"(a[2]), "r"(a[3]), "r"(b0), "r"(b1));
}

// one k16 step of a (MF*16)x(NF*8) warp tile with hi/lo compensation
template<int MF, int NF>
__device__ __forceinline__ void mma_step(
    float (&acc)[MF][NF][4],
    const __nv_bfloat16* __restrict__ Ahi, const __nv_bfloat16* __restrict__ Alo, int KPa,
    const __nv_bfloat16* __restrict__ Whi, const __nv_bfloat16* __restrict__ Wlo, int KPw,
    int m0, int n0, int kbA, int kbW, int g, int t)
{
    unsigned ah[MF][4], al[MF][4];
#pragma unroll
    for (int mf = 0; mf < MF; mf++) {
        int r = m0 + mf * 16 + g;
        ah[mf][0] = *(const unsigned*)&Ahi[(r    ) * KPa + kbA     + t * 2];
        ah[mf][1] = *(const unsigned*)&Ahi[(r + 8) * KPa + kbA     + t * 2];
        ah[mf][2] = *(const unsigned*)&Ahi[(r    ) * KPa + kbA + 8 + t * 2];
        ah[mf][3] = *(const unsigned*)&Ahi[(r + 8) * KPa + kbA + 8 + t * 2];
        al[mf][0] = *(const unsigned*)&Alo[(r    ) * KPa + kbA     + t * 2];
        al[mf][1] = *(const unsigned*)&Alo[(r + 8) * KPa + kbA     + t * 2];
        al[mf][2] = *(const unsigned*)&Alo[(r    ) * KPa + kbA + 8 + t * 2];
        al[mf][3] = *(const unsigned*)&Alo[(r + 8) * KPa + kbA + 8 + t * 2];
    }
#pragma unroll
    for (int nf = 0; nf < NF; nf++) {
        int n = n0 + nf * 8 + g;
        unsigned bh0 = *(const unsigned*)&Whi[n * KPw + kbW     + t * 2];
        unsigned bh1 = *(const unsigned*)&Whi[n * KPw + kbW + 8 + t * 2];
        unsigned bl0 = *(const unsigned*)&Wlo[n * KPw + kbW     + t * 2];
        unsigned bl1 = *(const unsigned*)&Wlo[n * KPw + kbW + 8 + t * 2];
#pragma unroll
        for (int mf = 0; mf < MF; mf++) {
            mma_bf16(acc[mf][nf], ah[mf], bh0, bh1);
            mma_bf16(acc[mf][nf], ah[mf], bl0, bl1);
            mma_bf16(acc[mf][nf], al[mf], bh0, bh1);
        }
    }
}

// ---------------- prep: zero degree + split feat + split weights -------------
__global__ void prep_kernel(const float* __restrict__ feat,
                            const float* __restrict__ W1, const float* __restrict__ W2,
                            const float* __restrict__ Wm1, const float* __restrict__ Wm2) {
    unsigned i = blockIdx.x * blockDim.x + threadIdx.x;
    if (i < N_NODES) g_cnt_i[i] = 0;
    if (i < N_NODES * D_IN / 2) {
        float2 v = __ldg(((const float2*)feat) + i);
        __nv_bfloat16 h0, l0, h1, l1;
        split2(v.x, h0, l0); split2(v.y, h1, l1);
        *(unsigned*)&g_fhi[i * 2] = pack_bf2(h0, h1);
        *(unsigned*)&g_flo[i * 2] = pack_bf2(l0, l1);
    }
    if (i < 92160) {
        __nv_bfloat16 h, l;
        if (i < 16384) {                        // W1 [128k][128n]
            int k = i >> 7, n = i & 127;
            split2(__ldg(&W1[i]), h, l);
            g_w1hi[n * KP128 + k] = h; g_w1lo[n * KP128 + k] = l;
        } else if (i < 49152) {                 // W2 [256k][128n]
            int j = i - 16384; int k = j >> 7, n = j & 127;
            split2(__ldg(&W2[j]), h, l);
            g_w2hi[n * KP256 + k] = h; g_w2lo[n * KP256 + k] = l;
        } else if (i < 81920) {                 // Wm1 [128k][256n]
            int j = i - 49152; int k = j >> 8, n = j & 255;
            split2(__ldg(&Wm1[j]), h, l);
            g_m1hi[n * KP128 + k] = h; g_m1lo[n * KP128 + k] = l;
        } else {                                // Wm2 [256k][40n]
            int j = i - 81920; int k = j / 40, n = j % 40;
            split2(__ldg(&Wm2[j]), h, l);
            g_m2hi[n * KP256 + k] = h; g_m2lo[n * KP256 + k] = l;
        }
    }
}

// ---------------- CSR build --------------------------------------------------
__global__ void hist_kernel(const int* __restrict__ ei) {
    unsigned e = blockIdx.x * blockDim.x + threadIdx.x;
    if (e >= N_EDGES) return;
    int s = __ldg(&ei[e]);
    int d = __ldg(&ei[N_EDGES + e]);
    if ((unsigned)s >= (unsigned)N_NODES || (unsigned)d >= (unsigned)N_NODES) return;
    atomicAdd(&g_cnt_i[d], 1);
}
__global__ void scan1_kernel() {
    __shared__ int sm[256];
    int t = threadIdx.x, b = blockIdx.x;
    int i = b * 256 + t;
    int v = (i < N_NODES) ? g_cnt_i[i] : 0;
    sm[t] = v; __syncthreads();
    for (int off = 1; off < 256; off <<= 1) {
        int x = (t >= off) ? sm[t - off] : 0;
        __syncthreads(); sm[t] += x; __syncthreads();
    }
    if (i < N_NODES) g_rs[i] = sm[t] - v;
    if (t == 255) g_bsum[b] = sm[255];
}
__global__ void scan23_kernel() {           // per-block lookback + finalize
    __shared__ int red[256];
    int t = threadIdx.x, b = blockIdx.x;
    int partial = 0;
    for (int j = t; j < b; j += 256) partial += g_bsum[j];
    red[t] = partial; __syncthreads();
    for (int off = 128; off > 0; off >>= 1) {
        if (t < off) red[t] += red[t + off];
        __syncthreads();
    }
    int base = red[0];
    int i = b * 256 + t;
    if (i < N_NODES) {
        int v = g_rs[i] + base;
        g_rs[i] = v;
        g_wr[i] = v;
    }
}
__global__ void fill_kernel(const int* __restrict__ ei) {
    unsigned e = blockIdx.x * blockDim.x + threadIdx.x;
    if (e >= N_EDGES) return;
    int s = __ldg(&ei[e]);
    int d = __ldg(&ei[N_EDGES + e]);
    if ((unsigned)s >= (unsigned)N_NODES || (unsigned)d >= (unsigned)N_NODES) return;
    g_adj[atomicAdd(&g_wr[d], 1)] = s;
}

// ============================================================================
// Layer-1 (gather fused): h1 = sigmoid([feat | mean_neigh(feat)] @ W1 + b1)
// M=64/blk, N=128, K=128, 2-occ.
// ============================================================================
#define L1_SMEM ((2 * 64 * KP128 + 2 * 128 * KP128) * 2)
__global__ void __launch_bounds__(256, 2)
l1_mma_kernel(const float* __restrict__ feat, const float* __restrict__ b1) {
    extern __shared__ unsigned char smraw[];
    __nv_bfloat16* Ahi = (__nv_bfloat16*)smraw;        // [64][KP128]
    __nv_bfloat16* Alo = Ahi + 64 * KP128;
    __nv_bfloat16* Whi = Alo + 64 * KP128;             // [128][KP128]
    __nv_bfloat16* Wlo = Whi + 128 * KP128;
    int tid = threadIdx.x;
    int node0 = blockIdx.x * 64;
    int w = tid >> 5, lane = tid & 31;

    for (int i = tid; i < 128 * KP128 / 8; i += 256) {   // W blob copy (uint4)
        ((uint4*)Whi)[i] = ((const uint4*)g_w1hi)[i];
        ((uint4*)Wlo)[i] = ((const uint4*)g_w1lo)[i];
    }
    for (int i = tid; i < 64 * 8; i += 256) {            // A cols 0..63 = feat
        int r = i >> 3, q = i & 7;
        int gn = node0 + r;
        uint4 vh = make_uint4(0,0,0,0), vl = vh;
        if (gn < N_NODES) {
            vh = ((const uint4*)(g_fhi + (size_t)gn * D_IN))[q];
            vl = ((const uint4*)(g_flo + (size_t)gn * D_IN))[q];
        }
        *(uint4*)&Ahi[r * KP128 + q * 8] = vh;
        *(uint4*)&Alo[r * KP128 + q * 8] = vl;
    }
    // gather: warp w handles nodes w, w+8, ..., w+56; lane covers 2 feat dims
#pragma unroll
    for (int j = 0; j < 8; j++) {
        int nd = w + j * 8;
        int gn = node0 + nd;
        float2 acc = make_float2(0.f, 0.f);
        int deg = 0;
        if (gn < N_NODES) {
            deg = g_cnt_i[gn];
            int start = g_rs[gn];
            for (int e = 0; e < deg; e++) {
                int s = __ldg(&g_adj[start + e]);
                float2 v = __ldg((const float2*)(feat + (size_t)s * D_IN) + lane);
                acc.x += v.x; acc.y += v.y;
            }
        }
        float rcp = 1.0f / fmaxf((float)deg, 1.0f);
        acc.x *= rcp; acc.y *= rcp;
        __nv_bfloat16 h0, l0, h1, l1; split2(acc.x, h0, l0); split2(acc.y, h1, l1);
        *(unsigned*)&Ahi[nd * KP128 + 64 + lane * 2] = pack_bf2(h0, h1);
        *(unsigned*)&Alo[nd * KP128 + 64 + lane * 2] = pack_bf2(l0, l1);
    }
    __syncthreads();

    int g = lane >> 2, t = lane & 3;
    int m0 = (w & 3) * 16, n0 = (w >> 2) * 64;
    float acc[1][8][4];
#pragma unroll
    for (int b = 0; b < 8; b++)
#pragma unroll
        for (int c = 0; c < 4; c++) acc[0][b][c] = 0.f;

#pragma unroll
    for (int ks = 0; ks < 8; ks++)
        mma_step<1, 8>(acc, Ahi, Alo, KP128, Whi, Wlo, KP128,
                       m0, n0, ks * 16, ks * 16, g, t);

    int r0 = node0 + m0 + g;
#pragma unroll
    for (int nf = 0; nf < 8; nf++) {
        int col = n0 + nf * 8 + t * 2;
        float2 bv = *(const float2*)&b1[col];
        if (r0 < N_NODES) {
            float v0 = sigmoidf_(acc[0][nf][0] + bv.x);
            float v1 = sigmoidf_(acc[0][nf][1] + bv.y);
            __nv_bfloat16 h0, l0, h1, l1; split2(v0, h0, l0); split2(v1, h1, l1);
            size_t idx = (size_t)r0 * D_H + col;
            *(unsigned*)&g_h1hi[idx] = pack_bf2(h0, h1);
            *(unsigned*)&g_h1lo[idx] = pack_bf2(l0, l1);
        }
        if (r0 + 8 < N_NODES) {
            float v0 = sigmoidf_(acc[0][nf][2] + bv.x);
            float v1 = sigmoidf_(acc[0][nf][3] + bv.y);
            __nv_bfloat16 h0, l0, h1, l1; split2(v0, h0, l0); split2(v1, h1, l1);
            size_t idx = (size_t)(r0 + 8) * D_H + col;
            *(unsigned*)&g_h1hi[idx] = pack_bf2(h0, h1);
            *(unsigned*)&g_h1lo[idx] = pack_bf2(l0, l1);
        }
    }
}

// ============================================================================
// Fused gather2 + L2 + MLP1 + MLP2 (M=64/blk, 2-occ).
//   kc0: A = h1-self, W = W2[:,k0:128]  -> MMA
//   kc1: A = mean_neigh(h1) (gathered in-kernel), W = W2[:,128:256] -> MMA
//   epilogue -> h2 into A buffer
//   per n-half: h3half = relu(h2 @ Wm1half + bm1) -> W rows 0..63
//               acc2 += h3half @ Wm2half   (warps 0-3)
//   out = acc2 + bm2
// ============================================================================
#define F_SMEM ((2 * 64 * KP128 + 2 * 128 * KP128) * 2)
__global__ void __launch_bounds__(256, 2)
fused_l2_mlp_kernel(const float* __restrict__ b2, const float* __restrict__ bm1,
                    const float* __restrict__ bm2, float* __restrict__ out) {
    extern __shared__ unsigned char smraw[];
    __nv_bfloat16* Ahi = (__nv_bfloat16*)smraw;        // [64][KP128]
    __nv_bfloat16* Alo = Ahi + 64 * KP128;
    __nv_bfloat16* Whi = Alo + 64 * KP128;             // [128][KP128]
    __nv_bfloat16* Wlo = Whi + 128 * KP128;
    int tid = threadIdx.x;
    int node0 = blockIdx.x * 64;
    int w = tid >> 5, lane = tid & 31, g = lane >> 2, t = lane & 3;
    int m0 = (w & 3) * 16, n0 = (w >> 2) * 64;

    float acc[1][8][4];
#pragma unroll
    for (int b = 0; b < 8; b++)
#pragma unroll
        for (int c = 0; c < 4; c++) acc[0][b][c] = 0.f;

    // ---- kc0: W2 chunk 0 + A = h1 self ----
    for (int i = tid; i < 128 * 16; i += 256) {
        int n = i >> 4, q = i & 15;
        *(uint4*)&Whi[n * KP128 + q * 8] = *(const uint4*)&g_w2hi[n * KP256 + q * 8];
        *(uint4*)&Wlo[n * KP128 + q * 8] = *(const uint4*)&g_w2lo[n * KP256 + q * 8];
    }
    for (int i = tid; i < 64 * 16; i += 256) {
        int r = i >> 4, q = i & 15;
        int gn = node0 + r;
        uint4 vh = make_uint4(0,0,0,0), vl = vh;
        if (gn < N_NODES) {
            vh = ((const uint4*)(g_h1hi + (size_t)gn * D_H))[q];
            vl = ((const uint4*)(g_h1lo + (size_t)gn * D_H))[q];
        }
        *(uint4*)&Ahi[r * KP128 + q * 8] = vh;
        *(uint4*)&Alo[r * KP128 + q * 8] = vl;
    }
    __syncthreads();
#pragma unroll
    for (int ks = 0; ks < 8; ks++)
        mma_step<1, 8>(acc, Ahi, Alo, KP128, Whi, Wlo, KP128,
                       m0, n0, ks * 16, ks * 16, g, t);
    __syncthreads();   // A free for gather overwrite

    // ---- kc1: W2 chunk 1 + A = mean_neigh(h1), gathered in-kernel ----
    for (int i = tid; i < 128 * 16; i += 256) {
        int n = i >> 4, q = i & 15;
        *(uint4*)&Whi[n * KP128 + q * 8] = *(const uint4*)&g_w2hi[n * KP256 + 128 + q * 8];
        *(uint4*)&Wlo[n * KP128 + q * 8] = *(const uint4*)&g_w2lo[n * KP256 + 128 + q * 8];
    }
#pragma unroll
    for (int j = 0; j < 8; j++) {          // warp w: nodes w+8j; lane: 4 dims
        int nd = w + j * 8;
        int gn = node0 + nd;
        float4 a4 = make_float4(0.f, 0.f, 0.f, 0.f);
        int deg = 0;
        if (gn < N_NODES) {
            deg = g_cnt_i[gn];
            int start = g_rs[gn];
            for (int e = 0; e < deg; e++) {
                int s = __ldg(&g_adj[start + e]);
                size_t off = (size_t)s * D_H + lane * 4;
                uint2 vh = *(const uint2*)(g_h1hi + off);
                uint2 vl = *(const uint2*)(g_h1lo + off);
                float2 p = bf2f2(vh.x), q2 = bf2f2(vh.y), r2 = bf2f2(vl.x), s2 = bf2f2(vl.y);
                a4.x += p.x + r2.x; a4.y += p.y + r2.y;
                a4.z += q2.x + s2.x; a4.w += q2.y + s2.y;
            }
        }
        float rcp = 1.0f / fmaxf((float)deg, 1.0f);
        a4.x *= rcp; a4.y *= rcp; a4.z *= rcp; a4.w *= rcp;
        __nv_bfloat16 h0,l0,h1,l1,h2,l2,h3,l3;
        split2(a4.x,h0,l0); split2(a4.y,h1,l1); split2(a4.z,h2,l2); split2(a4.w,h3,l3);
        *(uint2*)&Ahi[nd * KP128 + lane * 4] = make_uint2(pack_bf2(h0,h1), pack_bf2(h2,h3));
        *(uint2*)&Alo[nd * KP128 + lane * 4] = make_uint2(pack_bf2(l0,l1), pack_bf2(l2,l3));
    }
    __syncthreads();
#pragma unroll
    for (int ks = 0; ks < 8; ks++)
        mma_step<1, 8>(acc, Ahi, Alo, KP128, Whi, Wlo, KP128,
                       m0, n0, ks * 16, ks * 16, g, t);
    __syncthreads();     // all warps done reading A before overwriting with h2

    // epilogue A: h2 -> A buffer (sigmoid + split), rows are block-local
    {
        int rr = m0 + g;
#pragma unroll
        for (int nf = 0; nf < 8; nf++) {
            int col = n0 + nf * 8 + t * 2;
            float2 bv = *(const float2*)&b2[col];
            float v0 = sigmoidf_(acc[0][nf][0] + bv.x);
            float v1 = sigmoidf_(acc[0][nf][1] + bv.y);
            float v2 = sigmoidf_(acc[0][nf][2] + bv.x);
            float v3 = sigmoidf_(acc[0][nf][3] + bv.y);
            __nv_bfloat16 h0, l0, h1, l1; split2(v0, h0, l0); split2(v1, h1, l1);
            *(unsigned*)&Ahi[rr * KP128 + col] = pack_bf2(h0, h1);
            *(unsigned*)&Alo[rr * KP128 + col] = pack_bf2(l0, l1);
            split2(v2, h0, l0); split2(v3, h1, l1);
            *(unsigned*)&Ahi[(rr + 8) * KP128 + col] = pack_bf2(h0, h1);
            *(unsigned*)&Alo[(rr + 8) * KP128 + col] = pack_bf2(l0, l1);
        }
    }
    __syncthreads();

    // ---------------- phase B: MLP1 half + MLP2 partial, per nb -------------
    float acc2[1][5][4];
#pragma unroll
    for (int b = 0; b < 5; b++)
#pragma unroll
        for (int c = 0; c < 4; c++) acc2[0][b][c] = 0.f;

    for (int nb = 0; nb < 2; nb++) {
        if (nb) __syncthreads();
        {   // stage Wm1 half nb (blob copy)
            const uint4* srcH = (const uint4*)(g_m1hi + nb * 128 * KP128);
            const uint4* srcL = (const uint4*)(g_m1lo + nb * 128 * KP128);
            for (int i = tid; i < 128 * KP128 / 8; i += 256) {
                ((uint4*)Whi)[i] = srcH[i];
                ((uint4*)Wlo)[i] = srcL[i];
            }
        }
        __syncthreads();

        float acc1[1][8][4];
#pragma unroll
        for (int b = 0; b < 8; b++)
#pragma unroll
            for (int c = 0; c < 4; c++) acc1[0][b][c] = 0.f;

#pragma unroll
        for (int ks = 0; ks < 8; ks++)
            mma_step<1, 8>(acc1, Ahi, Alo, KP128, Whi, Wlo, KP128,
                           m0, n0, ks * 16, ks * 16, g, t);
        __syncthreads();     // done reading Wm1 half; W buffer reusable

        // epilogue B1: h3half = relu(acc1 + bm1) -> W buffer rows 0..63
        {
            int rr = m0 + g;
#pragma unroll
            for (int nf = 0; nf < 8; nf++) {
                int colL = n0 + nf * 8 + t * 2;          // local 0..127
                float2 bv = *(const float2*)&bm1[nb * 128 + colL];
                float v0 = fmaxf(acc1[0][nf][0] + bv.x, 0.f);
                float v1 = fmaxf(acc1[0][nf][1] + bv.y, 0.f);
                float v2 = fmaxf(acc1[0][nf][2] + bv.x, 0.f);
                float v3 = fmaxf(acc1[0][nf][3] + bv.y, 0.f);
                __nv_bfloat16 h0, l0, h1, l1; split2(v0, h0, l0); split2(v1, h1, l1);
                *(unsigned*)&Whi[rr * KP128 + colL] = pack_bf2(h0, h1);
                *(unsigned*)&Wlo[rr * KP128 + colL] = pack_bf2(l0, l1);
                split2(v2, h0, l0); split2(v3, h1, l1);
                *(unsigned*)&Whi[(rr + 8) * KP128 + colL] = pack_bf2(h0, h1);
                *(unsigned*)&Wlo[(rr + 8) * KP128 + colL] = pack_bf2(l0, l1);
            }
        }
        // stage Wm2 k-half nb into W rows 64..103
        for (int i = tid; i < 40 * 16; i += 256) {
            int n = i >> 4, q = i & 15;
            *(uint4*)&Whi[(64 + n) * KP128 + q * 8] =
                *(const uint4*)&g_m2hi[n * KP256 + nb * 128 + q * 8];
            *(uint4*)&Wlo[(64 + n) * KP128 + q * 8] =
                *(const uint4*)&g_m2lo[n * KP256 + nb * 128 + q * 8];
        }
        __syncthreads();

        // m2 partial: warps 0-3, A = h3half (W rows 0..63), B = Wm2 (W rows 64+)
        if (w < 4) {
            int m0b = w * 16;
#pragma unroll
            for (int ks = 0; ks < 8; ks++)
                mma_step<1, 5>(acc2, Whi, Wlo, KP128,
                               Whi + 64 * KP128, Wlo + 64 * KP128, KP128,
                               m0b, 0, ks * 16, ks * 16, g, t);
        }
    }

    // ---------------- final epilogue: out = acc2 + bm2 ----------------------
    if (w < 4) {
        int r0 = node0 + w * 16 + g;
#pragma unroll
        for (int nf = 0; nf < 5; nf++) {
            int col = nf * 8 + t * 2;
            float2 bv = *(const float2*)&bm2[col];
            if (r0 < N_NODES) {
                float2 o = make_float2(acc2[0][nf][0] + bv.x, acc2[0][nf][1] + bv.y);
                *(float2*)&out[(size_t)r0 * D_OUT + col] = o;
            }
            if (r0 + 8 < N_NODES) {
                float2 o = make_float2(acc2[0][nf][2] + bv.x, acc2[0][nf][3] + bv.y);
                *(float2*)&out[(size_t)(r0 + 8) * D_OUT + col] = o;
            }
        }
    }
}

// ---------------- launch -----------------------------------------------------
extern "C" void kernel_launch(void* const* d_in, const int* in_sizes, int n_in,
                              void* d_out, int out_size) {
    const float* feat = (const float*)d_in[0];
    const int*   ei   = (const int*)d_in[1];     // int32 (JAX x64 disabled)
    const float* W1   = (const float*)d_in[2];
    const float* b1   = (const float*)d_in[3];
    const float* W2   = (const float*)d_in[4];
    const float* b2   = (const float*)d_in[5];
    const float* Wm1  = (const float*)d_in[6];
    const float* bm1  = (const float*)d_in[7];
    const float* Wm2  = (const float*)d_in[8];
    const float* bm2  = (const float*)d_in[9];
    float* out = (float*)d_out;

    cudaFuncSetAttribute(l1_mma_kernel, cudaFuncAttributeMaxDynamicSharedMemorySize, L1_SMEM);
    cudaFuncSetAttribute(fused_l2_mlp_kernel, cudaFuncAttributeMaxDynamicSharedMemorySize, F_SMEM);

    // prep (zero degree + split feat + split weights)
    prep_kernel<<<(N_NODES * D_IN / 2 + 255) / 256, 256>>>(feat, W1, W2, Wm1, Wm2);

    // CSR build
    hist_kernel<<<(N_EDGES + 255) / 256, 256>>>(ei);
    scan1_kernel<<<NB_SCAN, 256>>>();
    scan23_kernel<<<NB_SCAN, 256>>>();
    fill_kernel<<<(N_EDGES + 255) / 256, 256>>>(ei);

    // layer 1 (gather fused)
    l1_mma_kernel<<<(N_NODES + 63) / 64, 256, L1_SMEM>>>(feat, b1);

    // layer 2 + MLP (gather fused)
    fused_l2_mlp_kernel<<<(N_NODES + 63) / 64, 256, F_SMEM>>>(b2, bm1, bm2, out);
}

// round 11
// speedup vs baseline: 1.2259x; 1.2259x over previous
#include <cuda_runtime.h>
#include <cuda_bf16.h>

#define N_NODES 100000
#define N_EDGES 1600000
#define D_IN    64
#define D_H     128
#define D_M     256
#define D_OUT   40
#define NB_SCAN 391   // ceil(N_NODES/256)
#define KP128 136
#define KP256 264

// ---------------- device-global scratch --------------------------------------
__device__ int g_cnt_i[N_NODES];
__device__ int g_rs  [N_NODES];
__device__ int g_wr  [N_NODES];
__device__ int g_bsum[512];
__device__ int g_adj [N_EDGES];
__device__ __align__(16) __nv_bfloat16 g_fhi [(size_t)N_NODES * D_IN];
__device__ __align__(16) __nv_bfloat16 g_flo [(size_t)N_NODES * D_IN];
__device__ __align__(16) __nv_bfloat16 g_a1hi[(size_t)N_NODES * D_IN];
__device__ __align__(16) __nv_bfloat16 g_a1lo[(size_t)N_NODES * D_IN];
__device__ __align__(16) __nv_bfloat16 g_a2hi[(size_t)N_NODES * D_H];
__device__ __align__(16) __nv_bfloat16 g_a2lo[(size_t)N_NODES * D_H];
__device__ __align__(16) __nv_bfloat16 g_h1hi[(size_t)N_NODES * D_H];
__device__ __align__(16) __nv_bfloat16 g_h1lo[(size_t)N_NODES * D_H];
// pre-split weights, padded to smem tile layout (n-major, stride KP*)
__device__ __align__(16) __nv_bfloat16 g_w1hi[128 * KP128], g_w1lo[128 * KP128];
__device__ __align__(16) __nv_bfloat16 g_w2hi[128 * KP256], g_w2lo[128 * KP256];
__device__ __align__(16) __nv_bfloat16 g_m1hi[256 * KP128], g_m1lo[256 * KP128];
__device__ __align__(16) __nv_bfloat16 g_m2hi[ 40 * KP256], g_m2lo[ 40 * KP256];

// ---------------- helpers ----------------------------------------------------
__device__ __forceinline__ float sigmoidf_(float x) {
    return 1.0f / (1.0f + __expf(-x));
}
__device__ __forceinline__ void split2(float x, __nv_bfloat16& hi, __nv_bfloat16& lo) {
    hi = __float2bfloat16(x);
    lo = __float2bfloat16(x - __bfloat162float(hi));
}
__device__ __forceinline__ unsigned pack_bf2(__nv_bfloat16 a, __nv_bfloat16 b) {
    return (unsigned)__bfloat16_as_ushort(a) | ((unsigned)__bfloat16_as_ushort(b) << 16);
}
__device__ __forceinline__ float2 bf2f2(unsigned u) {
    __nv_bfloat162 b = *(__nv_bfloat162*)&u;
    return __bfloat1622float2(b);
}

__device__ __forceinline__ void mma_bf16(float c[4], const unsigned a[4],
                                         unsigned b0, unsigned b1) {
    asm volatile("mma.sync.aligned.m16n8k16.row.col.f32.bf16.bf16.f32 "
                 "{%0,%1,%2,%3}, {%4,%5,%6,%7}, {%8,%9}, {%0,%1,%2,%3};"
                 : "+f"(c[0]), "+f"(c[1]), "+f"(c[2]), "+f"(c[3])
                 : "r"(a[0]), "r"(a[1]), "r"(a[2]), "r"(a[3]), "r"(b0), "r"(b1));
}

// one k16 step of a (MF*16)x(NF*8) warp tile with hi/lo compensation
template<int MF, int NF>
__device__ __forceinline__ void mma_step(
    float (&acc)[MF][NF][4],
    const __nv_bfloat16* __restrict__ Ahi, const __nv_bfloat16* __restrict__ Alo, int KPa,
    const __nv_bfloat16* __restrict__ Whi, const __nv_bfloat16* __restrict__ Wlo, int KPw,
    int m0, int n0, int kbA, int kbW, int g, int t)
{
    unsigned ah[MF][4], al[MF][4];
#pragma unroll
    for (int mf = 0; mf < MF; mf++) {
        int r = m0 + mf * 16 + g;
        ah[mf][0] = *(const unsigned*)&Ahi[(r    ) * KPa + kbA     + t * 2];
        ah[mf][1] = *(const unsigned*)&Ahi[(r + 8) * KPa + kbA     + t * 2];
        ah[mf][2] = *(const unsigned*)&Ahi[(r    ) * KPa + kbA + 8 + t * 2];
        ah[mf][3] = *(const unsigned*)&Ahi[(r + 8) * KPa + kbA + 8 + t * 2];
        al[mf][0] = *(const unsigned*)&Alo[(r    ) * KPa + kbA     + t * 2];
        al[mf][1] = *(const unsigned*)&Alo[(r + 8) * KPa + kbA     + t * 2];
        al[mf][2] = *(const unsigned*)&Alo[(r    ) * KPa + kbA + 8 + t * 2];
        al[mf][3] = *(const unsigned*)&Alo[(r + 8) * KPa + kbA + 8 + t * 2];
    }
#pragma unroll
    for (int nf = 0; nf < NF; nf++) {
        int n = n0 + nf * 8 + g;
        unsigned bh0 = *(const unsigned*)&Whi[n * KPw + kbW     + t * 2];
        unsigned bh1 = *(const unsigned*)&Whi[n * KPw + kbW + 8 + t * 2];
        unsigned bl0 = *(const unsigned*)&Wlo[n * KPw + kbW     + t * 2];
        unsigned bl1 = *(const unsigned*)&Wlo[n * KPw + kbW + 8 + t * 2];
#pragma unroll
        for (int mf = 0; mf < MF; mf++) {
            mma_bf16(acc[mf][nf], ah[mf], bh0, bh1);
            mma_bf16(acc[mf][nf], ah[mf], bl0, bl1);
            mma_bf16(acc[mf][nf], al[mf], bh0, bh1);
        }
    }
}

// ---------------- prep: zero degree + split feat + split weights -------------
__global__ void prep_kernel(const float* __restrict__ feat,
                            const float* __restrict__ W1, const float* __restrict__ W2,
                            const float* __restrict__ Wm1, const float* __restrict__ Wm2) {
    unsigned i = blockIdx.x * blockDim.x + threadIdx.x;
    if (i < N_NODES) g_cnt_i[i] = 0;
    if (i < N_NODES * D_IN / 2) {
        float2 v = __ldg(((const float2*)feat) + i);
        __nv_bfloat16 h0, l0, h1, l1;
        split2(v.x, h0, l0); split2(v.y, h1, l1);
        *(unsigned*)&g_fhi[i * 2] = pack_bf2(h0, h1);
        *(unsigned*)&g_flo[i * 2] = pack_bf2(l0, l1);
    }
    if (i < 92160) {
        __nv_bfloat16 h, l;
        if (i < 16384) {                        // W1 [128k][128n]
            int k = i >> 7, n = i & 127;
            split2(__ldg(&W1[i]), h, l);
            g_w1hi[n * KP128 + k] = h; g_w1lo[n * KP128 + k] = l;
        } else if (i < 49152) {                 // W2 [256k][128n]
            int j = i - 16384; int k = j >> 7, n = j & 127;
            split2(__ldg(&W2[j]), h, l);
            g_w2hi[n * KP256 + k] = h; g_w2lo[n * KP256 + k] = l;
        } else if (i < 81920) {                 // Wm1 [128k][256n]
            int j = i - 49152; int k = j >> 8, n = j & 255;
            split2(__ldg(&Wm1[j]), h, l);
            g_m1hi[n * KP128 + k] = h; g_m1lo[n * KP128 + k] = l;
        } else {                                // Wm2 [256k][40n]
            int j = i - 81920; int k = j / 40, n = j % 40;
            split2(__ldg(&Wm2[j]), h, l);
            g_m2hi[n * KP256 + k] = h; g_m2lo[n * KP256 + k] = l;
        }
    }
}

// ---------------- CSR build --------------------------------------------------
__global__ void hist_kernel(const int* __restrict__ ei) {
    unsigned e = blockIdx.x * blockDim.x + threadIdx.x;
    if (e >= N_EDGES) return;
    int s = __ldg(&ei[e]);
    int d = __ldg(&ei[N_EDGES + e]);
    if ((unsigned)s >= (unsigned)N_NODES || (unsigned)d >= (unsigned)N_NODES) return;
    atomicAdd(&g_cnt_i[d], 1);
}
__global__ void scan1_kernel() {
    __shared__ int sm[256];
    int t = threadIdx.x, b = blockIdx.x;
    int i = b * 256 + t;
    int v = (i < N_NODES) ? g_cnt_i[i] : 0;
    sm[t] = v; __syncthreads();
    for (int off = 1; off < 256; off <<= 1) {
        int x = (t >= off) ? sm[t - off] : 0;
        __syncthreads(); sm[t] += x; __syncthreads();
    }
    if (i < N_NODES) g_rs[i] = sm[t] - v;
    if (t == 255) g_bsum[b] = sm[255];
}
__global__ void scan23_kernel() {           // per-block lookback + finalize
    __shared__ int red[256];
    int t = threadIdx.x, b = blockIdx.x;
    int partial = 0;
    for (int j = t; j < b; j += 256) partial += g_bsum[j];
    red[t] = partial; __syncthreads();
    for (int off = 128; off > 0; off >>= 1) {
        if (t < off) red[t] += red[t + off];
        __syncthreads();
    }
    int base = red[0];
    int i = b * 256 + t;
    if (i < N_NODES) {
        int v = g_rs[i] + base;
        g_rs[i] = v;
        g_wr[i] = v;
    }
}
__global__ void fill_kernel(const int* __restrict__ ei) {
    unsigned e = blockIdx.x * blockDim.x + threadIdx.x;
    if (e >= N_EDGES) return;
    int s = __ldg(&ei[e]);
    int d = __ldg(&ei[N_EDGES + e]);
    if ((unsigned)s >= (unsigned)N_NODES || (unsigned)d >= (unsigned)N_NODES) return;
    g_adj[atomicAdd(&g_wr[d], 1)] = s;
}

// ---------------- gather-reduce (warp per node) ------------------------------
__global__ void gather1_kernel(const float* __restrict__ feat) {
    int warp = (blockIdx.x * blockDim.x + threadIdx.x) >> 5;
    int lane = threadIdx.x & 31;
    if (warp >= N_NODES) return;
    int deg = g_cnt_i[warp], start = g_rs[warp];
    float2 acc = make_float2(0.f, 0.f);
    for (int j = 0; j < deg; j++) {
        int s = __ldg(&g_adj[start + j]);
        float2 v = __ldg((const float2*)(feat + (size_t)s * D_IN) + lane);
        acc.x += v.x; acc.y += v.y;
    }
    float rcp = 1.0f / fmaxf((float)deg, 1.0f);
    acc.x *= rcp; acc.y *= rcp;
    __nv_bfloat16 h0, l0, h1, l1; split2(acc.x, h0, l0); split2(acc.y, h1, l1);
    size_t idx = (size_t)warp * D_IN + lane * 2;
    *(unsigned*)&g_a1hi[idx] = pack_bf2(h0, h1);
    *(unsigned*)&g_a1lo[idx] = pack_bf2(l0, l1);
}

__global__ void gather2_kernel() {
    int warp = (blockIdx.x * blockDim.x + threadIdx.x) >> 5;
    int lane = threadIdx.x & 31;
    if (warp >= N_NODES) return;
    int deg = g_cnt_i[warp], start = g_rs[warp];
    float4 acc = make_float4(0.f, 0.f, 0.f, 0.f);
    for (int j = 0; j < deg; j++) {
        int s = __ldg(&g_adj[start + j]);
        size_t off = (size_t)s * D_H + lane * 4;
        uint2 vh = *(const uint2*)(g_h1hi + off);
        uint2 vl = *(const uint2*)(g_h1lo + off);
        float2 a = bf2f2(vh.x), b = bf2f2(vh.y), c = bf2f2(vl.x), d = bf2f2(vl.y);
        acc.x += a.x + c.x; acc.y += a.y + c.y;
        acc.z += b.x + d.x; acc.w += b.y + d.y;
    }
    float rcp = 1.0f / fmaxf((float)deg, 1.0f);
    acc.x *= rcp; acc.y *= rcp; acc.z *= rcp; acc.w *= rcp;
    __nv_bfloat16 h0,l0,h1,l1,h2,l2,h3,l3;
    split2(acc.x,h0,l0); split2(acc.y,h1,l1); split2(acc.z,h2,l2); split2(acc.w,h3,l3);
    size_t idx = (size_t)warp * D_H + lane * 4;
    *(uint2*)&g_a2hi[idx] = make_uint2(pack_bf2(h0,h1), pack_bf2(h2,h3));
    *(uint2*)&g_a2lo[idx] = make_uint2(pack_bf2(l0,l1), pack_bf2(l2,l3));
}

// ============================================================================
// Layer-1: h1 = sigmoid([feat | a1] @ W1 + b1)  (M=64/blk, N=128, K=128, 2-occ)
// ============================================================================
#define L1_SMEM ((2 * 64 * KP128 + 2 * 128 * KP128) * 2)
__global__ void __launch_bounds__(256, 2)
l1_mma_kernel(const float* __restrict__ b1) {
    extern __shared__ unsigned char smraw[];
    __nv_bfloat16* Ahi = (__nv_bfloat16*)smraw;        // [64][KP128]
    __nv_bfloat16* Alo = Ahi + 64 * KP128;
    __nv_bfloat16* Whi = Alo + 64 * KP128;             // [128][KP128]
    __nv_bfloat16* Wlo = Whi + 128 * KP128;
    int tid = threadIdx.x;
    int node0 = blockIdx.x * 64;

    for (int i = tid; i < 128 * KP128 / 8; i += 256) {   // W blob copy (uint4)
        ((uint4*)Whi)[i] = ((const uint4*)g_w1hi)[i];
        ((uint4*)Wlo)[i] = ((const uint4*)g_w1lo)[i];
    }
    for (int i = tid; i < 64 * 8; i += 256) {            // A cols 0..63 = feat
        int r = i >> 3, q = i & 7;
        int gn = node0 + r;
        uint4 vh = make_uint4(0,0,0,0), vl = vh;
        if (gn < N_NODES) {
            vh = ((const uint4*)(g_fhi + (size_t)gn * D_IN))[q];
            vl = ((const uint4*)(g_flo + (size_t)gn * D_IN))[q];
        }
        *(uint4*)&Ahi[r * KP128 + q * 8] = vh;
        *(uint4*)&Alo[r * KP128 + q * 8] = vl;
    }
    for (int i = tid; i < 64 * 8; i += 256) {            // A cols 64..127 = a1
        int r = i >> 3, q = i & 7;
        int gn = node0 + r;
        uint4 vh = make_uint4(0,0,0,0), vl = vh;
        if (gn < N_NODES) {
            vh = ((const uint4*)(g_a1hi + (size_t)gn * D_IN))[q];
            vl = ((const uint4*)(g_a1lo + (size_t)gn * D_IN))[q];
        }
        *(uint4*)&Ahi[r * KP128 + 64 + q * 8] = vh;
        *(uint4*)&Alo[r * KP128 + 64 + q * 8] = vl;
    }
    __syncthreads();

    int w = tid >> 5, lane = tid & 31, g = lane >> 2, t = lane & 3;
    int m0 = (w & 3) * 16, n0 = (w >> 2) * 64;
    float acc[1][8][4];
#pragma unroll
    for (int b = 0; b < 8; b++)
#pragma unroll
        for (int c = 0; c < 4; c++) acc[0][b][c] = 0.f;

#pragma unroll
    for (int ks = 0; ks < 8; ks++)
        mma_step<1, 8>(acc, Ahi, Alo, KP128, Whi, Wlo, KP128,
                       m0, n0, ks * 16, ks * 16, g, t);

    int r0 = node0 + m0 + g;
#pragma unroll
    for (int nf = 0; nf < 8; nf++) {
        int col = n0 + nf * 8 + t * 2;
        float2 bv = *(const float2*)&b1[col];
        if (r0 < N_NODES) {
            float v0 = sigmoidf_(acc[0][nf][0] + bv.x);
            float v1 = sigmoidf_(acc[0][nf][1] + bv.y);
            __nv_bfloat16 h0, l0, h1, l1; split2(v0, h0, l0); split2(v1, h1, l1);
            size_t idx = (size_t)r0 * D_H + col;
            *(unsigned*)&g_h1hi[idx] = pack_bf2(h0, h1);
            *(unsigned*)&g_h1lo[idx] = pack_bf2(l0, l1);
        }
        if (r0 + 8 < N_NODES) {
            float v0 = sigmoidf_(acc[0][nf][2] + bv.x);
            float v1 = sigmoidf_(acc[0][nf][3] + bv.y);
            __nv_bfloat16 h0, l0, h1, l1; split2(v0, h0, l0); split2(v1, h1, l1);
            size_t idx = (size_t)(r0 + 8) * D_H + col;
            *(unsigned*)&g_h1hi[idx] = pack_bf2(h0, h1);
            *(unsigned*)&g_h1lo[idx] = pack_bf2(l0, l1);
        }
    }
}

// ============================================================================
// Fused L2 + MLP1 + MLP2 (M=64/blk, 2-occ).  h2 and h3 never leave smem.
// ============================================================================
#define F_SMEM ((2 * 64 * KP128 + 2 * 128 * KP128) * 2)
__global__ void __launch_bounds__(256, 2)
fused_l2_mlp_kernel(const float* __restrict__ b2, const float* __restrict__ bm1,
                    const float* __restrict__ bm2, float* __restrict__ out) {
    extern __shared__ unsigned char smraw[];
    __nv_bfloat16* Ahi = (__nv_bfloat16*)smraw;        // [64][KP128]
    __nv_bfloat16* Alo = Ahi + 64 * KP128;
    __nv_bfloat16* Whi = Alo + 64 * KP128;             // [128][KP128]
    __nv_bfloat16* Wlo = Whi + 128 * KP128;
    int tid = threadIdx.x;
    int node0 = blockIdx.x * 64;
    int w = tid >> 5, lane = tid & 31, g = lane >> 2, t = lane & 3;
    int m0 = (w & 3) * 16, n0 = (w >> 2) * 64;

    // ---------------- phase A: layer-2 GEMM ----------------
    float acc[1][8][4];
#pragma unroll
    for (int b = 0; b < 8; b++)
#pragma unroll
        for (int c = 0; c < 4; c++) acc[0][b][c] = 0.f;

    for (int kc = 0; kc < 2; kc++) {
        if (kc) __syncthreads();
        for (int i = tid; i < 128 * 16; i += 256) {    // W2 chunk rows
            int n = i >> 4, q = i & 15;
            *(uint4*)&Whi[n * KP128 + q * 8] =
                *(const uint4*)&g_w2hi[n * KP256 + kc * 128 + q * 8];
            *(uint4*)&Wlo[n * KP128 + q * 8] =
                *(const uint4*)&g_w2lo[n * KP256 + kc * 128 + q * 8];
        }
        const __nv_bfloat16* srcHi = kc ? g_a2hi : g_h1hi;
        const __nv_bfloat16* srcLo = kc ? g_a2lo : g_h1lo;
        for (int i = tid; i < 64 * 16; i += 256) {     // A chunk = h1 / a2
            int r = i >> 4, q = i & 15;
            int gn = node0 + r;
            uint4 vh = make_uint4(0,0,0,0), vl = vh;
            if (gn < N_NODES) {
                vh = ((const uint4*)(srcHi + (size_t)gn * D_H))[q];
                vl = ((const uint4*)(srcLo + (size_t)gn * D_H))[q];
            }
            *(uint4*)&Ahi[r * KP128 + q * 8] = vh;
            *(uint4*)&Alo[r * KP128 + q * 8] = vl;
        }
        __syncthreads();
#pragma unroll
        for (int ks = 0; ks < 8; ks++)
            mma_step<1, 8>(acc, Ahi, Alo, KP128, Whi, Wlo, KP128,
                           m0, n0, ks * 16, ks * 16, g, t);
    }
    __syncthreads();     // all warps done reading A before overwriting with h2

    // epilogue A: h2 -> A buffer (sigmoid + split), rows are block-local
    {
        int rr = m0 + g;
#pragma unroll
        for (int nf = 0; nf < 8; nf++) {
            int col = n0 + nf * 8 + t * 2;
            float2 bv = *(const float2*)&b2[col];
            float v0 = sigmoidf_(acc[0][nf][0] + bv.x);
            float v1 = sigmoidf_(acc[0][nf][1] + bv.y);
            float v2 = sigmoidf_(acc[0][nf][2] + bv.x);
            float v3 = sigmoidf_(acc[0][nf][3] + bv.y);
            __nv_bfloat16 h0, l0, h1, l1; split2(v0, h0, l0); split2(v1, h1, l1);
            *(unsigned*)&Ahi[rr * KP128 + col] = pack_bf2(h0, h1);
            *(unsigned*)&Alo[rr * KP128 + col] = pack_bf2(l0, l1);
            split2(v2, h0, l0); split2(v3, h1, l1);
            *(unsigned*)&Ahi[(rr + 8) * KP128 + col] = pack_bf2(h0, h1);
            *(unsigned*)&Alo[(rr + 8) * KP128 + col] = pack_bf2(l0, l1);
        }
    }
    __syncthreads();

    // ---------------- phase B: MLP1 half + MLP2 partial, per nb -------------
    float acc2[1][5][4];
#pragma unroll
    for (int b = 0; b < 5; b++)
#pragma unroll
        for (int c = 0; c < 4; c++) acc2[0][b][c] = 0.f;

    for (int nb = 0; nb < 2; nb++) {
        if (nb) __syncthreads();
        {   // stage Wm1 half nb (blob copy)
            const uint4* srcH = (const uint4*)(g_m1hi + nb * 128 * KP128);
            const uint4* srcL = (const uint4*)(g_m1lo + nb * 128 * KP128);
            for (int i = tid; i < 128 * KP128 / 8; i += 256) {
                ((uint4*)Whi)[i] = srcH[i];
                ((uint4*)Wlo)[i] = srcL[i];
            }
        }
        __syncthreads();

        float acc1[1][8][4];
#pragma unroll
        for (int b = 0; b < 8; b++)
#pragma unroll
            for (int c = 0; c < 4; c++) acc1[0][b][c] = 0.f;

#pragma unroll
        for (int ks = 0; ks < 8; ks++)
            mma_step<1, 8>(acc1, Ahi, Alo, KP128, Whi, Wlo, KP128,
                           m0, n0, ks * 16, ks * 16, g, t);
        __syncthreads();     // done reading Wm1 half; W buffer reusable

        // epilogue B1: h3half = relu(acc1 + bm1) -> W buffer rows 0..63
        {
            int rr = m0 + g;
#pragma unroll
            for (int nf = 0; nf < 8; nf++) {
                int colL = n0 + nf * 8 + t * 2;          // local 0..127
                float2 bv = *(const float2*)&bm1[nb * 128 + colL];
                float v0 = fmaxf(acc1[0][nf][0] + bv.x, 0.f);
                float v1 = fmaxf(acc1[0][nf][1] + bv.y, 0.f);
                float v2 = fmaxf(acc1[0][nf][2] + bv.x, 0.f);
                float v3 = fmaxf(acc1[0][nf][3] + bv.y, 0.f);
                __nv_bfloat16 h0, l0, h1, l1; split2(v0, h0, l0); split2(v1, h1, l1);
                *(unsigned*)&Whi[rr * KP128 + colL] = pack_bf2(h0, h1);
                *(unsigned*)&Wlo[rr * KP128 + colL] = pack_bf2(l0, l1);
                split2(v2, h0, l0); split2(v3, h1, l1);
                *(unsigned*)&Whi[(rr + 8) * KP128 + colL] = pack_bf2(h0, h1);
                *(unsigned*)&Wlo[(rr + 8) * KP128 + colL] = pack_bf2(l0, l1);
            }
        }
        // stage Wm2 k-half nb into W rows 64..103
        for (int i = tid; i < 40 * 16; i += 256) {
            int n = i >> 4, q = i & 15;
            *(uint4*)&Whi[(64 + n) * KP128 + q * 8] =
                *(const uint4*)&g_m2hi[n * KP256 + nb * 128 + q * 8];
            *(uint4*)&Wlo[(64 + n) * KP128 + q * 8] =
                *(const uint4*)&g_m2lo[n * KP256 + nb * 128 + q * 8];
        }
        __syncthreads();

        // m2 partial: warps 0-3, A = h3half (W rows 0..63), B = Wm2 (W rows 64+)
        if (w < 4) {
            int m0b = w * 16;
#pragma unroll
            for (int ks = 0; ks < 8; ks++)
                mma_step<1, 5>(acc2, Whi, Wlo, KP128,
                               Whi + 64 * KP128, Wlo + 64 * KP128, KP128,
                               m0b, 0, ks * 16, ks * 16, g, t);
        }
    }

    // ---------------- final epilogue: out = acc2 + bm2 ----------------------
    if (w < 4) {
        int r0 = node0 + w * 16 + g;
#pragma unroll
        for (int nf = 0; nf < 5; nf++) {
            int col = nf * 8 + t * 2;
            float2 bv = *(const float2*)&bm2[col];
            if (r0 < N_NODES) {
                float2 o = make_float2(acc2[0][nf][0] + bv.x, acc2[0][nf][1] + bv.y);
                *(float2*)&out[(size_t)r0 * D_OUT + col] = o;
            }
            if (r0 + 8 < N_NODES) {
                float2 o = make_float2(acc2[0][nf][2] + bv.x, acc2[0][nf][3] + bv.y);
                *(float2*)&out[(size_t)(r0 + 8) * D_OUT + col] = o;
            }
        }
    }
}

// ---------------- launch -----------------------------------------------------
extern "C" void kernel_launch(void* const* d_in, const int* in_sizes, int n_in,
                              void* d_out, int out_size) {
    const float* feat = (const float*)d_in[0];
    const int*   ei   = (const int*)d_in[1];     // int32 (JAX x64 disabled)
    const float* W1   = (const float*)d_in[2];
    const float* b1   = (const float*)d_in[3];
    const float* W2   = (const float*)d_in[4];
    const float* b2   = (const float*)d_in[5];
    const float* Wm1  = (const float*)d_in[6];
    const float* bm1  = (const float*)d_in[7];
    const float* Wm2  = (const float*)d_in[8];
    const float* bm2  = (const float*)d_in[9];
    float* out = (float*)d_out;

    cudaFuncSetAttribute(l1_mma_kernel, cudaFuncAttributeMaxDynamicSharedMemorySize, L1_SMEM);
    cudaFuncSetAttribute(fused_l2_mlp_kernel, cudaFuncAttributeMaxDynamicSharedMemorySize, F_SMEM);

    // prep (zero degree + split feat + split weights) — one launch
    prep_kernel<<<(N_NODES * D_IN / 2 + 255) / 256, 256>>>(feat, W1, W2, Wm1, Wm2);

    // CSR build
    hist_kernel<<<(N_EDGES + 255) / 256, 256>>>(ei);
    scan1_kernel<<<NB_SCAN, 256>>>();
    scan23_kernel<<<NB_SCAN, 256>>>();
    fill_kernel<<<(N_EDGES + 255) / 256, 256>>>(ei);

    // layer 1
    gather1_kernel<<<(N_NODES * 32 + 255) / 256, 256>>>(feat);
    l1_mma_kernel<<<(N_NODES + 63) / 64, 256, L1_SMEM>>>(b1);

    // layer 2 + MLP (fused)
    gather2_kernel<<<(N_NODES * 32 + 255) / 256, 256>>>();
    fused_l2_mlp_kernel<<<(N_NODES + 63) / 64, 256, F_SMEM>>>(b2, bm1, bm2, out);
}

// round 12
// speedup vs baseline: 1.3434x; 1.0959x over previous
#include <cuda_runtime.h>
#include <cuda_bf16.h>
#include <cuda_fp16.h>

#define N_NODES 100000
#define N_EDGES 1600000
#define D_IN    64
#define D_H     128
#define D_M     256
#define D_OUT   40
#define NB_SCAN 391   // ceil(N_NODES/256)
#define KP128 136
#define KP256 264

// ---------------- device-global scratch --------------------------------------
__device__ int g_cnt_i[N_NODES];
__device__ int g_rs  [N_NODES];
__device__ int g_wr  [N_NODES];
__device__ int g_bsum[512];
__device__ int g_adj [N_EDGES];
__device__ __align__(16) __nv_bfloat16 g_fhi [(size_t)N_NODES * D_IN];
__device__ __align__(16) __nv_bfloat16 g_flo [(size_t)N_NODES * D_IN];
__device__ __align__(16) __half        g_f16 [(size_t)N_NODES * D_IN];   // fp16 feat (neighbor reads)
__device__ __align__(16) __half        g_h1f [(size_t)N_NODES * D_H];    // fp16 h1
__device__ __align__(16) __nv_bfloat16 g_a1hi[(size_t)N_NODES * D_IN];
__device__ __align__(16) __nv_bfloat16 g_a1lo[(size_t)N_NODES * D_IN];
__device__ __align__(16) __nv_bfloat16 g_a2hi[(size_t)N_NODES * D_H];
__device__ __align__(16) __nv_bfloat16 g_a2lo[(size_t)N_NODES * D_H];
// pre-split weights, padded to smem tile layout (n-major, stride KP*)
__device__ __align__(16) __nv_bfloat16 g_w1hi[128 * KP128], g_w1lo[128 * KP128];
__device__ __align__(16) __nv_bfloat16 g_w2hi[128 * KP256], g_w2lo[128 * KP256];
__device__ __align__(16) __nv_bfloat16 g_m1hi[256 * KP128], g_m1lo[256 * KP128];
__device__ __align__(16) __nv_bfloat16 g_m2hi[ 40 * KP256], g_m2lo[ 40 * KP256];

// ---------------- helpers ----------------------------------------------------
__device__ __forceinline__ float sigmoidf_(float x) {
    return 1.0f / (1.0f + __expf(-x));
}
__device__ __forceinline__ void split2(float x, __nv_bfloat16& hi, __nv_bfloat16& lo) {
    hi = __float2bfloat16(x);
    lo = __float2bfloat16(x - __bfloat162float(hi));
}
__device__ __forceinline__ unsigned pack_bf2(__nv_bfloat16 a, __nv_bfloat16 b) {
    return (unsigned)__bfloat16_as_ushort(a) | ((unsigned)__bfloat16_as_ushort(b) << 16);
}
__device__ __forceinline__ float2 bf2f2(unsigned u) {
    __nv_bfloat162 b = *(__nv_bfloat162*)&u;
    return __bfloat1622float2(b);
}

__device__ __forceinline__ void mma_bf16(float c[4], const unsigned a[4],
                                         unsigned b0, unsigned b1) {
    asm volatile("mma.sync.aligned.m16n8k16.row.col.f32.bf16.bf16.f32 "
                 "{%0,%1,%2,%3}, {%4,%5,%6,%7}, {%8,%9}, {%0,%1,%2,%3};"
                 : "+f"(c[0]), "+f"(c[1]), "+f"(c[2]), "+f"(c[3])
                 : "r"(a[0]), "r"(a[1]), "r"(a[2]), "r"(a[3]), "r"(b0), "r"(b1));
}

// one k16 step of a (MF*16)x(NF*8) warp tile with hi/lo compensation
template<int MF, int NF>
__device__ __forceinline__ void mma_step(
    float (&acc)[MF][NF][4],
    const __nv_bfloat16* __restrict__ Ahi, const __nv_bfloat16* __restrict__ Alo, int KPa,
    const __nv_bfloat16* __restrict__ Whi, const __nv_bfloat16* __restrict__ Wlo, int KPw,
    int m0, int n0, int kbA, int kbW, int g, int t)
{
    unsigned ah[MF][4], al[MF][4];
#pragma unroll
    for (int mf = 0; mf < MF; mf++) {
        int r = m0 + mf * 16 + g;
        ah[mf][0] = *(const unsigned*)&Ahi[(r    ) * KPa + kbA     + t * 2];
        ah[mf][1] = *(const unsigned*)&Ahi[(r + 8) * KPa + kbA     + t * 2];
        ah[mf][2] = *(const unsigned*)&Ahi[(r    ) * KPa + kbA + 8 + t * 2];
        ah[mf][3] = *(const unsigned*)&Ahi[(r + 8) * KPa + kbA + 8 + t * 2];
        al[mf][0] = *(const unsigned*)&Alo[(r    ) * KPa + kbA     + t * 2];
        al[mf][1] = *(const unsigned*)&Alo[(r + 8) * KPa + kbA     + t * 2];
        al[mf][2] = *(const unsigned*)&Alo[(r    ) * KPa + kbA + 8 + t * 2];
        al[mf][3] = *(const unsigned*)&Alo[(r + 8) * KPa + kbA + 8 + t * 2];
    }
#pragma unroll
    for (int nf = 0; nf < NF; nf++) {
        int n = n0 + nf * 8 + g;
        unsigned bh0 = *(const unsigned*)&Whi[n * KPw + kbW     + t * 2];
        unsigned bh1 = *(const unsigned*)&Whi[n * KPw + kbW + 8 + t * 2];
        unsigned bl0 = *(const unsigned*)&Wlo[n * KPw + kbW     + t * 2];
        unsigned bl1 = *(const unsigned*)&Wlo[n * KPw + kbW + 8 + t * 2];
#pragma unroll
        for (int mf = 0; mf < MF; mf++) {
            mma_bf16(acc[mf][nf], ah[mf], bh0, bh1);
            mma_bf16(acc[mf][nf], ah[mf], bl0, bl1);
            mma_bf16(acc[mf][nf], al[mf], bh0, bh1);
        }
    }
}

// ---------------- prep: zero degree + split feat + split weights -------------
__global__ void prep_kernel(const float* __restrict__ feat,
                            const float* __restrict__ W1, const float* __restrict__ W2,
                            const float* __restrict__ Wm1, const float* __restrict__ Wm2) {
    unsigned i = blockIdx.x * blockDim.x + threadIdx.x;
    if (i < N_NODES) g_cnt_i[i] = 0;
    if (i < N_NODES * D_IN / 2) {
        float2 v = __ldg(((const float2*)feat) + i);
        __nv_bfloat16 h0, l0, h1, l1;
        split2(v.x, h0, l0); split2(v.y, h1, l1);
        *(unsigned*)&g_fhi[i * 2] = pack_bf2(h0, h1);
        *(unsigned*)&g_flo[i * 2] = pack_bf2(l0, l1);
        *(__half2*)&g_f16[i * 2] = __floats2half2_rn(v.x, v.y);
    }
    if (i < 92160) {
        __nv_bfloat16 h, l;
        if (i < 16384) {                        // W1 [128k][128n]
            int k = i >> 7, n = i & 127;
            split2(__ldg(&W1[i]), h, l);
            g_w1hi[n * KP128 + k] = h; g_w1lo[n * KP128 + k] = l;
        } else if (i < 49152) {                 // W2 [256k][128n]
            int j = i - 16384; int k = j >> 7, n = j & 127;
            split2(__ldg(&W2[j]), h, l);
            g_w2hi[n * KP256 + k] = h; g_w2lo[n * KP256 + k] = l;
        } else if (i < 81920) {                 // Wm1 [128k][256n]
            int j = i - 49152; int k = j >> 8, n = j & 255;
            split2(__ldg(&Wm1[j]), h, l);
            g_m1hi[n * KP128 + k] = h; g_m1lo[n * KP128 + k] = l;
        } else {                                // Wm2 [256k][40n]
            int j = i - 81920; int k = j / 40, n = j % 40;
            split2(__ldg(&Wm2[j]), h, l);
            g_m2hi[n * KP256 + k] = h; g_m2lo[n * KP256 + k] = l;
        }
    }
}

// ---------------- CSR build --------------------------------------------------
__global__ void hist_kernel(const int* __restrict__ ei) {
    unsigned e = blockIdx.x * blockDim.x + threadIdx.x;
    if (e >= N_EDGES) return;
    int s = __ldg(&ei[e]);
    int d = __ldg(&ei[N_EDGES + e]);
    if ((unsigned)s >= (unsigned)N_NODES || (unsigned)d >= (unsigned)N_NODES) return;
    atomicAdd(&g_cnt_i[d], 1);
}
__global__ void scan1_kernel() {
    __shared__ int sm[256];
    int t = threadIdx.x, b = blockIdx.x;
    int i = b * 256 + t;
    int v = (i < N_NODES) ? g_cnt_i[i] : 0;
    sm[t] = v; __syncthreads();
    for (int off = 1; off < 256; off <<= 1) {
        int x = (t >= off) ? sm[t - off] : 0;
        __syncthreads(); sm[t] += x; __syncthreads();
    }
    if (i < N_NODES) g_rs[i] = sm[t] - v;
    if (t == 255) g_bsum[b] = sm[255];
}
__global__ void scan23_kernel() {           // per-block lookback + finalize
    __shared__ int red[256];
    int t = threadIdx.x, b = blockIdx.x;
    int partial = 0;
    for (int j = t; j < b; j += 256) partial += g_bsum[j];
    red[t] = partial; __syncthreads();
    for (int off = 128; off > 0; off >>= 1) {
        if (t < off) red[t] += red[t + off];
        __syncthreads();
    }
    int base = red[0];
    int i = b * 256 + t;
    if (i < N_NODES) {
        int v = g_rs[i] + base;
        g_rs[i] = v;
        g_wr[i] = v;
    }
}
__global__ void fill_kernel(const int* __restrict__ ei) {
    unsigned e = blockIdx.x * blockDim.x + threadIdx.x;
    if (e >= N_EDGES) return;
    int s = __ldg(&ei[e]);
    int d = __ldg(&ei[N_EDGES + e]);
    if ((unsigned)s >= (unsigned)N_NODES || (unsigned)d >= (unsigned)N_NODES) return;
    g_adj[atomicAdd(&g_wr[d], 1)] = s;
}

// ---------------- gather-reduce (warp per node) ------------------------------
__global__ void gather1_kernel() {
    int warp = (blockIdx.x * blockDim.x + threadIdx.x) >> 5;
    int lane = threadIdx.x & 31;
    if (warp >= N_NODES) return;
    int deg = g_cnt_i[warp], start = g_rs[warp];
    float2 acc = make_float2(0.f, 0.f);
    for (int j = 0; j < deg; j++) {
        int s = __ldg(&g_adj[start + j]);
        __half2 v = *(const __half2*)(g_f16 + (size_t)s * D_IN + lane * 2);
        float2 f = __half22float2(v);
        acc.x += f.x; acc.y += f.y;
    }
    float rcp = 1.0f / fmaxf((float)deg, 1.0f);
    acc.x *= rcp; acc.y *= rcp;
    __nv_bfloat16 h0, l0, h1, l1; split2(acc.x, h0, l0); split2(acc.y, h1, l1);
    size_t idx = (size_t)warp * D_IN + lane * 2;
    *(unsigned*)&g_a1hi[idx] = pack_bf2(h0, h1);
    *(unsigned*)&g_a1lo[idx] = pack_bf2(l0, l1);
}

__global__ void gather2_kernel() {
    int warp = (blockIdx.x * blockDim.x + threadIdx.x) >> 5;
    int lane = threadIdx.x & 31;
    if (warp >= N_NODES) return;
    int deg = g_cnt_i[warp], start = g_rs[warp];
    float4 acc = make_float4(0.f, 0.f, 0.f, 0.f);
    for (int j = 0; j < deg; j++) {
        int s = __ldg(&g_adj[start + j]);
        uint2 v = *(const uint2*)(g_h1f + (size_t)s * D_H + lane * 4);
        float2 a = __half22float2(*(__half2*)&v.x);
        float2 b = __half22float2(*(__half2*)&v.y);
        acc.x += a.x; acc.y += a.y; acc.z += b.x; acc.w += b.y;
    }
    float rcp = 1.0f / fmaxf((float)deg, 1.0f);
    acc.x *= rcp; acc.y *= rcp; acc.z *= rcp; acc.w *= rcp;
    __nv_bfloat16 h0,l0,h1,l1,h2,l2,h3,l3;
    split2(acc.x,h0,l0); split2(acc.y,h1,l1); split2(acc.z,h2,l2); split2(acc.w,h3,l3);
    size_t idx = (size_t)warp * D_H + lane * 4;
    *(uint2*)&g_a2hi[idx] = make_uint2(pack_bf2(h0,h1), pack_bf2(h2,h3));
    *(uint2*)&g_a2lo[idx] = make_uint2(pack_bf2(l0,l1), pack_bf2(l2,l3));
}

// ============================================================================
// Layer-1: h1 = sigmoid([feat | a1] @ W1 + b1)  (M=64/blk, N=128, K=128, 2-occ)
// ============================================================================
#define L1_SMEM ((2 * 64 * KP128 + 2 * 128 * KP128) * 2)
__global__ void __launch_bounds__(256, 2)
l1_mma_kernel(const float* __restrict__ b1) {
    extern __shared__ unsigned char smraw[];
    __nv_bfloat16* Ahi = (__nv_bfloat16*)smraw;        // [64][KP128]
    __nv_bfloat16* Alo = Ahi + 64 * KP128;
    __nv_bfloat16* Whi = Alo + 64 * KP128;             // [128][KP128]
    __nv_bfloat16* Wlo = Whi + 128 * KP128;
    int tid = threadIdx.x;
    int node0 = blockIdx.x * 64;

    for (int i = tid; i < 128 * KP128 / 8; i += 256) {   // W blob copy (uint4)
        ((uint4*)Whi)[i] = ((const uint4*)g_w1hi)[i];
        ((uint4*)Wlo)[i] = ((const uint4*)g_w1lo)[i];
    }
    for (int i = tid; i < 64 * 8; i += 256) {            // A cols 0..63 = feat
        int r = i >> 3, q = i & 7;
        int gn = node0 + r;
        uint4 vh = make_uint4(0,0,0,0), vl = vh;
        if (gn < N_NODES) {
            vh = ((const uint4*)(g_fhi + (size_t)gn * D_IN))[q];
            vl = ((const uint4*)(g_flo + (size_t)gn * D_IN))[q];
        }
        *(uint4*)&Ahi[r * KP128 + q * 8] = vh;
        *(uint4*)&Alo[r * KP128 + q * 8] = vl;
    }
    for (int i = tid; i < 64 * 8; i += 256) {            // A cols 64..127 = a1
        int r = i >> 3, q = i & 7;
        int gn = node0 + r;
        uint4 vh = make_uint4(0,0,0,0), vl = vh;
        if (gn < N_NODES) {
            vh = ((const uint4*)(g_a1hi + (size_t)gn * D_IN))[q];
            vl = ((const uint4*)(g_a1lo + (size_t)gn * D_IN))[q];
        }
        *(uint4*)&Ahi[r * KP128 + 64 + q * 8] = vh;
        *(uint4*)&Alo[r * KP128 + 64 + q * 8] = vl;
    }
    __syncthreads();

    int w = tid >> 5, lane = tid & 31, g = lane >> 2, t = lane & 3;
    int m0 = (w & 3) * 16, n0 = (w >> 2) * 64;
    float acc[1][8][4];
#pragma unroll
    for (int b = 0; b < 8; b++)
#pragma unroll
        for (int c = 0; c < 4; c++) acc[0][b][c] = 0.f;

#pragma unroll
    for (int ks = 0; ks < 8; ks++)
        mma_step<1, 8>(acc, Ahi, Alo, KP128, Whi, Wlo, KP128,
                       m0, n0, ks * 16, ks * 16, g, t);

    int r0 = node0 + m0 + g;
#pragma unroll
    for (int nf = 0; nf < 8; nf++) {
        int col = n0 + nf * 8 + t * 2;
        float2 bv = *(const float2*)&b1[col];
        if (r0 < N_NODES) {
            float v0 = sigmoidf_(acc[0][nf][0] + bv.x);
            float v1 = sigmoidf_(acc[0][nf][1] + bv.y);
            *(__half2*)&g_h1f[(size_t)r0 * D_H + col] = __floats2half2_rn(v0, v1);
        }
        if (r0 + 8 < N_NODES) {
            float v0 = sigmoidf_(acc[0][nf][2] + bv.x);
            float v1 = sigmoidf_(acc[0][nf][3] + bv.y);
            *(__half2*)&g_h1f[(size_t)(r0 + 8) * D_H + col] = __floats2half2_rn(v0, v1);
        }
    }
}

// ============================================================================
// Fused L2 + MLP1 + MLP2 (M=64/blk, 2-occ).  h2 and h3 never leave smem.
// ============================================================================
#define F_SMEM ((2 * 64 * KP128 + 2 * 128 * KP128) * 2)
__global__ void __launch_bounds__(256, 2)
fused_l2_mlp_kernel(const float* __restrict__ b2, const float* __restrict__ bm1,
                    const float* __restrict__ bm2, float* __restrict__ out) {
    extern __shared__ unsigned char smraw[];
    __nv_bfloat16* Ahi = (__nv_bfloat16*)smraw;        // [64][KP128]
    __nv_bfloat16* Alo = Ahi + 64 * KP128;
    __nv_bfloat16* Whi = Alo + 64 * KP128;             // [128][KP128]
    __nv_bfloat16* Wlo = Whi + 128 * KP128;
    int tid = threadIdx.x;
    int node0 = blockIdx.x * 64;
    int w = tid >> 5, lane = tid & 31, g = lane >> 2, t = lane & 3;
    int m0 = (w & 3) * 16, n0 = (w >> 2) * 64;

    // ---------------- phase A: layer-2 GEMM ----------------
    float acc[1][8][4];
#pragma unroll
    for (int b = 0; b < 8; b++)
#pragma unroll
        for (int c = 0; c < 4; c++) acc[0][b][c] = 0.f;

    for (int kc = 0; kc < 2; kc++) {
        if (kc) __syncthreads();
        for (int i = tid; i < 128 * 16; i += 256) {    // W2 chunk rows
            int n = i >> 4, q = i & 15;
            *(uint4*)&Whi[n * KP128 + q * 8] =
                *(const uint4*)&g_w2hi[n * KP256 + kc * 128 + q * 8];
            *(uint4*)&Wlo[n * KP128 + q * 8] =
                *(const uint4*)&g_w2lo[n * KP256 + kc * 128 + q * 8];
        }
        if (kc == 0) {
            // A chunk0 = h1 (fp16 -> split to hi/lo on the fly)
            for (int i = tid; i < 64 * 32; i += 256) {
                int r = i >> 5, q = i & 31;          // q = group of 4 dims
                int gn = node0 + r;
                uint2 v = make_uint2(0, 0);
                if (gn < N_NODES)
                    v = *(const uint2*)(g_h1f + (size_t)gn * D_H + q * 4);
                float2 f0 = __half22float2(*(__half2*)&v.x);
                float2 f1 = __half22float2(*(__half2*)&v.y);
                __nv_bfloat16 h0,l0,h1,l1,h2,l2,h3,l3;
                split2(f0.x,h0,l0); split2(f0.y,h1,l1);
                split2(f1.x,h2,l2); split2(f1.y,h3,l3);
                *(uint2*)&Ahi[r * KP128 + q * 4] = make_uint2(pack_bf2(h0,h1), pack_bf2(h2,h3));
                *(uint2*)&Alo[r * KP128 + q * 4] = make_uint2(pack_bf2(l0,l1), pack_bf2(l2,l3));
            }
        } else {
            // A chunk1 = a2 (pre-split copy)
            for (int i = tid; i < 64 * 16; i += 256) {
                int r = i >> 4, q = i & 15;
                int gn = node0 + r;
                uint4 vh = make_uint4(0,0,0,0), vl = vh;
                if (gn < N_NODES) {
                    vh = ((const uint4*)(g_a2hi + (size_t)gn * D_H))[q];
                    vl = ((const uint4*)(g_a2lo + (size_t)gn * D_H))[q];
                }
                *(uint4*)&Ahi[r * KP128 + q * 8] = vh;
                *(uint4*)&Alo[r * KP128 + q * 8] = vl;
            }
        }
        __syncthreads();
#pragma unroll
        for (int ks = 0; ks < 8; ks++)
            mma_step<1, 8>(acc, Ahi, Alo, KP128, Whi, Wlo, KP128,
                           m0, n0, ks * 16, ks * 16, g, t);
    }
    __syncthreads();     // all warps done reading A before overwriting with h2

    // epilogue A: h2 -> A buffer (sigmoid + split), rows are block-local
    {
        int rr = m0 + g;
#pragma unroll
        for (int nf = 0; nf < 8; nf++) {
            int col = n0 + nf * 8 + t * 2;
            float2 bv = *(const float2*)&b2[col];
            float v0 = sigmoidf_(acc[0][nf][0] + bv.x);
            float v1 = sigmoidf_(acc[0][nf][1] + bv.y);
            float v2 = sigmoidf_(acc[0][nf][2] + bv.x);
            float v3 = sigmoidf_(acc[0][nf][3] + bv.y);
            __nv_bfloat16 h0, l0, h1, l1; split2(v0, h0, l0); split2(v1, h1, l1);
            *(unsigned*)&Ahi[rr * KP128 + col] = pack_bf2(h0, h1);
            *(unsigned*)&Alo[rr * KP128 + col] = pack_bf2(l0, l1);
            split2(v2, h0, l0); split2(v3, h1, l1);
            *(unsigned*)&Ahi[(rr + 8) * KP128 + col] = pack_bf2(h0, h1);
            *(unsigned*)&Alo[(rr + 8) * KP128 + col] = pack_bf2(l0, l1);
        }
    }
    __syncthreads();

    // ---------------- phase B: MLP1 half + MLP2 partial, per nb -------------
    float acc2[1][5][4];
#pragma unroll
    for (int b = 0; b < 5; b++)
#pragma unroll
        for (int c = 0; c < 4; c++) acc2[0][b][c] = 0.f;

    for (int nb = 0; nb < 2; nb++) {
        if (nb) __syncthreads();
        {   // stage Wm1 half nb (blob copy)
            const uint4* srcH = (const uint4*)(g_m1hi + nb * 128 * KP128);
            const uint4* srcL = (const uint4*)(g_m1lo + nb * 128 * KP128);
            for (int i = tid; i < 128 * KP128 / 8; i += 256) {
                ((uint4*)Whi)[i] = srcH[i];
                ((uint4*)Wlo)[i] = srcL[i];
            }
        }
        __syncthreads();

        float acc1[1][8][4];
#pragma unroll
        for (int b = 0; b < 8; b++)
#pragma unroll
            for (int c = 0; c < 4; c++) acc1[0][b][c] = 0.f;

#pragma unroll
        for (int ks = 0; ks < 8; ks++)
            mma_step<1, 8>(acc1, Ahi, Alo, KP128, Whi, Wlo, KP128,
                           m0, n0, ks * 16, ks * 16, g, t);
        __syncthreads();     // done reading Wm1 half; W buffer reusable

        // epilogue B1: h3half = relu(acc1 + bm1) -> W buffer rows 0..63
        {
            int rr = m0 + g;
#pragma unroll
            for (int nf = 0; nf < 8; nf++) {
                int colL = n0 + nf * 8 + t * 2;          // local 0..127
                float2 bv = *(const float2*)&bm1[nb * 128 + colL];
                float v0 = fmaxf(acc1[0][nf][0] + bv.x, 0.f);
                float v1 = fmaxf(acc1[0][nf][1] + bv.y, 0.f);
                float v2 = fmaxf(acc1[0][nf][2] + bv.x, 0.f);
                float v3 = fmaxf(acc1[0][nf][3] + bv.y, 0.f);
                __nv_bfloat16 h0, l0, h1, l1; split2(v0, h0, l0); split2(v1, h1, l1);
                *(unsigned*)&Whi[rr * KP128 + colL] = pack_bf2(h0, h1);
                *(unsigned*)&Wlo[rr * KP128 + colL] = pack_bf2(l0, l1);
                split2(v2, h0, l0); split2(v3, h1, l1);
                *(unsigned*)&Whi[(rr + 8) * KP128 + colL] = pack_bf2(h0, h1);
                *(unsigned*)&Wlo[(rr + 8) * KP128 + colL] = pack_bf2(l0, l1);
            }
        }
        // stage Wm2 k-half nb into W rows 64..103
        for (int i = tid; i < 40 * 16; i += 256) {
            int n = i >> 4, q = i & 15;
            *(uint4*)&Whi[(64 + n) * KP128 + q * 8] =
                *(const uint4*)&g_m2hi[n * KP256 + nb * 128 + q * 8];
            *(uint4*)&Wlo[(64 + n) * KP128 + q * 8] =
                *(const uint4*)&g_m2lo[n * KP256 + nb * 128 + q * 8];
        }
        __syncthreads();

        // m2 partial: warps 0-3, A = h3half (W rows 0..63), B = Wm2 (W rows 64+)
        if (w < 4) {
            int m0b = w * 16;
#pragma unroll
            for (int ks = 0; ks < 8; ks++)
                mma_step<1, 5>(acc2, Whi, Wlo, KP128,
                               Whi + 64 * KP128, Wlo + 64 * KP128, KP128,
                               m0b, 0, ks * 16, ks * 16, g, t);
        }
    }

    // ---------------- final epilogue: out = acc2 + bm2 ----------------------
    if (w < 4) {
        int r0 = node0 + w * 16 + g;
#pragma unroll
        for (int nf = 0; nf < 5; nf++) {
            int col = nf * 8 + t * 2;
            float2 bv = *(const float2*)&bm2[col];
            if (r0 < N_NODES) {
                float2 o = make_float2(acc2[0][nf][0] + bv.x, acc2[0][nf][1] + bv.y);
                *(float2*)&out[(size_t)r0 * D_OUT + col] = o;
            }
            if (r0 + 8 < N_NODES) {
                float2 o = make_float2(acc2[0][nf][2] + bv.x, acc2[0][nf][3] + bv.y);
                *(float2*)&out[(size_t)(r0 + 8) * D_OUT + col] = o;
            }
        }
    }
}

// ---------------- launch -----------------------------------------------------
extern "C" void kernel_launch(void* const* d_in, const int* in_sizes, int n_in,
                              void* d_out, int out_size) {
    const float* feat = (const float*)d_in[0];
    const int*   ei   = (const int*)d_in[1];     // int32 (JAX x64 disabled)
    const float* W1   = (const float*)d_in[2];
    const float* b1   = (const float*)d_in[3];
    const float* W2   = (const float*)d_in[4];
    const float* b2   = (const float*)d_in[5];
    const float* Wm1  = (const float*)d_in[6];
    const float* bm1  = (const float*)d_in[7];
    const float* Wm2  = (const float*)d_in[8];
    const float* bm2  = (const float*)d_in[9];
    float* out = (float*)d_out;

    cudaFuncSetAttribute(l1_mma_kernel, cudaFuncAttributeMaxDynamicSharedMemorySize, L1_SMEM);
    cudaFuncSetAttribute(fused_l2_mlp_kernel, cudaFuncAttributeMaxDynamicSharedMemorySize, F_SMEM);

    // prep (zero degree + split feat + split weights) — one launch
    prep_kernel<<<(N_NODES * D_IN / 2 + 255) / 256, 256>>>(feat, W1, W2, Wm1, Wm2);

    // CSR build
    hist_kernel<<<(N_EDGES + 255) / 256, 256>>>(ei);
    scan1_kernel<<<NB_SCAN, 256>>>();
    scan23_kernel<<<NB_SCAN, 256>>>();
    fill_kernel<<<(N_EDGES + 255) / 256, 256>>>(ei);

    // layer 1
    gather1_kernel<<<(N_NODES * 32 + 255) / 256, 256>>>();
    l1_mma_kernel<<<(N_NODES + 63) / 64, 256, L1_SMEM>>>(b1);

    // layer 2 + MLP (fused)
    gather2_kernel<<<(N_NODES * 32 + 255) / 256, 256>>>();
    fused_l2_mlp_kernel<<<(N_NODES + 63) / 64, 256, F_SMEM>>>(b2, bm1, bm2, out);
}

// round 14
// speedup vs baseline: 1.3920x; 1.0361x over previous
#include <cuda_runtime.h>
#include <cuda_bf16.h>
#include <cuda_fp16.h>

#define N_NODES 100000
#define N_EDGES 1600000
#define D_IN    64
#define D_H     128
#define D_M     256
#define D_OUT   40
#define NB_SCAN 391   // ceil(N_NODES/256)
#define KP128 136
#define KP256 264
#define NT64   ((N_NODES + 63) / 64)   // 1563 node tiles
#define L1_GRID 296

// ---------------- device-global scratch --------------------------------------
__device__ int g_cnt_i[N_NODES];
__device__ int g_rs  [N_NODES];
__device__ int g_wr  [N_NODES];
__device__ int g_bsum[512];
__device__ int g_adj [N_EDGES];
__device__ __align__(16) __nv_bfloat16 g_fhi [(size_t)N_NODES * D_IN];
__device__ __align__(16) __nv_bfloat16 g_flo [(size_t)N_NODES * D_IN];
__device__ __align__(16) __half        g_f16 [(size_t)N_NODES * D_IN];   // fp16 feat (neighbor reads)
__device__ __align__(16) __half        g_h1f [(size_t)N_NODES * D_H];    // fp16 h1
__device__ __align__(16) __half        g_a1f [(size_t)N_NODES * D_IN];   // fp16 mean_neigh(feat)
__device__ __align__(16) __half        g_a2f [(size_t)N_NODES * D_H];    // fp16 mean_neigh(h1)
// pre-split weights, padded to smem tile layout (n-major, stride KP*)
__device__ __align__(16) __nv_bfloat16 g_w1hi[128 * KP128], g_w1lo[128 * KP128];
__device__ __align__(16) __nv_bfloat16 g_w2hi[128 * KP256], g_w2lo[128 * KP256];
__device__ __align__(16) __nv_bfloat16 g_m1hi[256 * KP128], g_m1lo[256 * KP128];
__device__ __align__(16) __nv_bfloat16 g_m2hi[ 40 * KP256], g_m2lo[ 40 * KP256];

// ---------------- helpers ----------------------------------------------------
__device__ __forceinline__ float sigmoidf_(float x) {
    return 1.0f / (1.0f + __expf(-x));
}
__device__ __forceinline__ void split2(float x, __nv_bfloat16& hi, __nv_bfloat16& lo) {
    hi = __float2bfloat16(x);
    lo = __float2bfloat16(x - __bfloat162float(hi));
}
__device__ __forceinline__ unsigned pack_bf2(__nv_bfloat16 a, __nv_bfloat16 b) {
    return (unsigned)__bfloat16_as_ushort(a) | ((unsigned)__bfloat16_as_ushort(b) << 16);
}

// convert 4 fp16 (uint2) -> hi/lo bf16 pairs (uint2 each)
__device__ __forceinline__ void h4_to_hilo(uint2 v, uint2& oh, uint2& ol) {
    float2 f0 = __half22float2(*(__half2*)&v.x);
    float2 f1 = __half22float2(*(__half2*)&v.y);
    __nv_bfloat16 h0,l0,h1,l1,h2,l2,h3,l3;
    split2(f0.x,h0,l0); split2(f0.y,h1,l1);
    split2(f1.x,h2,l2); split2(f1.y,h3,l3);
    oh = make_uint2(pack_bf2(h0,h1), pack_bf2(h2,h3));
    ol = make_uint2(pack_bf2(l0,l1), pack_bf2(l2,l3));
}

__device__ __forceinline__ void mma_bf16(float c[4], const unsigned a[4],
                                         unsigned b0, unsigned b1) {
    asm volatile("mma.sync.aligned.m16n8k16.row.col.f32.bf16.bf16.f32 "
                 "{%0,%1,%2,%3}, {%4,%5,%6,%7}, {%8,%9}, {%0,%1,%2,%3};"
                 : "+f"(c[0]), "+f"(c[1]), "+f"(c[2]), "+f"(c[3])
                 : "r"(a[0]), "r"(a[1]), "r"(a[2]), "r"(a[3]), "r"(b0), "r"(b1));
}

// one k16 step of a (MF*16)x(NF*8) warp tile with hi/lo compensation
template<int MF, int NF>
__device__ __forceinline__ void mma_step(
    float (&acc)[MF][NF][4],
    const __nv_bfloat16* __restrict__ Ahi, const __nv_bfloat16* __restrict__ Alo, int KPa,
    const __nv_bfloat16* __restrict__ Whi, const __nv_bfloat16* __restrict__ Wlo, int KPw,
    int m0, int n0, int kbA, int kbW, int g, int t)
{
    unsigned ah[MF][4], al[MF][4];
#pragma unroll
    for (int mf = 0; mf < MF; mf++) {
        int r = m0 + mf * 16 + g;
        ah[mf][0] = *(const unsigned*)&Ahi[(r    ) * KPa + kbA     + t * 2];
        ah[mf][1] = *(const unsigned*)&Ahi[(r + 8) * KPa + kbA     + t * 2];
        ah[mf][2] = *(const unsigned*)&Ahi[(r    ) * KPa + kbA + 8 + t * 2];
        ah[mf][3] = *(const unsigned*)&Ahi[(r + 8) * KPa + kbA + 8 + t * 2];
        al[mf][0] = *(const unsigned*)&Alo[(r    ) * KPa + kbA     + t * 2];
        al[mf][1] = *(const unsigned*)&Alo[(r + 8) * KPa + kbA     + t * 2];
        al[mf][2] = *(const unsigned*)&Alo[(r    ) * KPa + kbA + 8 + t * 2];
        al[mf][3] = *(const unsigned*)&Alo[(r + 8) * KPa + kbA + 8 + t * 2];
    }
#pragma unroll
    for (int nf = 0; nf < NF; nf++) {
        int n = n0 + nf * 8 + g;
        unsigned bh0 = *(const unsigned*)&Whi[n * KPw + kbW     + t * 2];
        unsigned bh1 = *(const unsigned*)&Whi[n * KPw + kbW + 8 + t * 2];
        unsigned bl0 = *(const unsigned*)&Wlo[n * KPw + kbW     + t * 2];
        unsigned bl1 = *(const unsigned*)&Wlo[n * KPw + kbW + 8 + t * 2];
#pragma unroll
        for (int mf = 0; mf < MF; mf++) {
            mma_bf16(acc[mf][nf], ah[mf], bh0, bh1);
            mma_bf16(acc[mf][nf], ah[mf], bl0, bl1);
            mma_bf16(acc[mf][nf], al[mf], bh0, bh1);
        }
    }
}

// ---------------- prep: zero degree + split feat + split weights -------------
__global__ void prep_kernel(const float* __restrict__ feat,
                            const float* __restrict__ W1, const float* __restrict__ W2,
                            const float* __restrict__ Wm1, const float* __restrict__ Wm2) {
    unsigned i = blockIdx.x * blockDim.x + threadIdx.x;
    if (i < N_NODES) g_cnt_i[i] = 0;
    if (i < N_NODES * D_IN / 2) {
        float2 v = __ldg(((const float2*)feat) + i);
        __nv_bfloat16 h0, l0, h1, l1;
        split2(v.x, h0, l0); split2(v.y, h1, l1);
        *(unsigned*)&g_fhi[i * 2] = pack_bf2(h0, h1);
        *(unsigned*)&g_flo[i * 2] = pack_bf2(l0, l1);
        *(__half2*)&g_f16[i * 2] = __floats2half2_rn(v.x, v.y);
    }
    if (i < 92160) {
        __nv_bfloat16 h, l;
        if (i < 16384) {                        // W1 [128k][128n]
            int k = i >> 7, n = i & 127;
            split2(__ldg(&W1[i]), h, l);
            g_w1hi[n * KP128 + k] = h; g_w1lo[n * KP128 + k] = l;
        } else if (i < 49152) {                 // W2 [256k][128n]
            int j = i - 16384; int k = j >> 7, n = j & 127;
            split2(__ldg(&W2[j]), h, l);
            g_w2hi[n * KP256 + k] = h; g_w2lo[n * KP256 + k] = l;
        } else if (i < 81920) {                 // Wm1 [128k][256n]
            int j = i - 49152; int k = j >> 8, n = j & 255;
            split2(__ldg(&Wm1[j]), h, l);
            g_m1hi[n * KP128 + k] = h; g_m1lo[n * KP128 + k] = l;
        } else {                                // Wm2 [256k][40n]
            int j = i - 81920; int k = j / 40, n = j % 40;
            split2(__ldg(&Wm2[j]), h, l);
            g_m2hi[n * KP256 + k] = h; g_m2lo[n * KP256 + k] = l;
        }
    }
}

// ---------------- CSR build --------------------------------------------------
__global__ void hist_kernel(const int* __restrict__ ei) {
    unsigned e = blockIdx.x * blockDim.x + threadIdx.x;
    if (e >= N_EDGES) return;
    int s = __ldg(&ei[e]);
    int d = __ldg(&ei[N_EDGES + e]);
    if ((unsigned)s >= (unsigned)N_NODES || (unsigned)d >= (unsigned)N_NODES) return;
    atomicAdd(&g_cnt_i[d], 1);
}
__global__ void scan1_kernel() {
    __shared__ int sm[256];
    int t = threadIdx.x, b = blockIdx.x;
    int i = b * 256 + t;
    int v = (i < N_NODES) ? g_cnt_i[i] : 0;
    sm[t] = v; __syncthreads();
    for (int off = 1; off < 256; off <<= 1) {
        int x = (t >= off) ? sm[t - off] : 0;
        __syncthreads(); sm[t] += x; __syncthreads();
    }
    if (i < N_NODES) g_rs[i] = sm[t] - v;
    if (t == 255) g_bsum[b] = sm[255];
}
__global__ void scan23_kernel() {           // per-block lookback + finalize
    __shared__ int red[256];
    int t = threadIdx.x, b = blockIdx.x;
    int partial = 0;
    for (int j = t; j < b; j += 256) partial += g_bsum[j];
    red[t] = partial; __syncthreads();
    for (int off = 128; off > 0; off >>= 1) {
        if (t < off) red[t] += red[t + off];
        __syncthreads();
    }
    int base = red[0];
    int i = b * 256 + t;
    if (i < N_NODES) {
        int v = g_rs[i] + base;
        g_rs[i] = v;
        g_wr[i] = v;
    }
}
__global__ void fill_kernel(const int* __restrict__ ei) {
    unsigned e = blockIdx.x * blockDim.x + threadIdx.x;
    if (e >= N_EDGES) return;
    int s = __ldg(&ei[e]);
    int d = __ldg(&ei[N_EDGES + e]);
    if ((unsigned)s >= (unsigned)N_NODES || (unsigned)d >= (unsigned)N_NODES) return;
    g_adj[atomicAdd(&g_wr[d], 1)] = s;
}

// ---------------- gather-reduce (warp per node), fp16 outputs ----------------
__global__ void gather1_kernel() {
    int warp = (blockIdx.x * blockDim.x + threadIdx.x) >> 5;
    int lane = threadIdx.x & 31;
    if (warp >= N_NODES) return;
    int deg = g_cnt_i[warp], start = g_rs[warp];
    float2 acc = make_float2(0.f, 0.f);
    for (int j = 0; j < deg; j++) {
        int s = __ldg(&g_adj[start + j]);
        __half2 v = *(const __half2*)(g_f16 + (size_t)s * D_IN + lane * 2);
        float2 f = __half22float2(v);
        acc.x += f.x; acc.y += f.y;
    }
    float rcp = 1.0f / fmaxf((float)deg, 1.0f);
    *(__half2*)&g_a1f[(size_t)warp * D_IN + lane * 2] =
        __floats2half2_rn(acc.x * rcp, acc.y * rcp);
}

__global__ void gather2_kernel() {
    int warp = (blockIdx.x * blockDim.x + threadIdx.x) >> 5;
    int lane = threadIdx.x & 31;
    if (warp >= N_NODES) return;
    int deg = g_cnt_i[warp], start = g_rs[warp];
    float4 acc = make_float4(0.f, 0.f, 0.f, 0.f);
    for (int j = 0; j < deg; j++) {
        int s = __ldg(&g_adj[start + j]);
        uint2 v = *(const uint2*)(g_h1f + (size_t)s * D_H + lane * 4);
        float2 a = __half22float2(*(__half2*)&v.x);
        float2 b = __half22float2(*(__half2*)&v.y);
        acc.x += a.x; acc.y += a.y; acc.z += b.x; acc.w += b.y;
    }
    float rcp = 1.0f / fmaxf((float)deg, 1.0f);
    uint2 o;
    *(__half2*)&o.x = __floats2half2_rn(acc.x * rcp, acc.y * rcp);
    *(__half2*)&o.y = __floats2half2_rn(acc.z * rcp, acc.w * rcp);
    *(uint2*)&g_a2f[(size_t)warp * D_H + lane * 4] = o;
}

// ============================================================================
// Layer-1 (persistent): h1 = sigmoid([feat | a1] @ W1 + b1)
// M=64/tile, N=128, K=128, 2-occ, W1 staged once per block.
// ============================================================================
#define L1_SMEM ((2 * 64 * KP128 + 2 * 128 * KP128) * 2)
__global__ void __launch_bounds__(256, 2)
l1_mma_kernel(const float* __restrict__ b1) {
    extern __shared__ unsigned char smraw[];
    __nv_bfloat16* Ahi = (__nv_bfloat16*)smraw;        // [64][KP128]
    __nv_bfloat16* Alo = Ahi + 64 * KP128;
    __nv_bfloat16* Whi = Alo + 64 * KP128;             // [128][KP128]
    __nv_bfloat16* Wlo = Whi + 128 * KP128;
    int tid = threadIdx.x;
    int w = tid >> 5, lane = tid & 31, g = lane >> 2, t = lane & 3;
    int m0 = (w & 3) * 16, n0 = (w >> 2) * 64;

    for (int i = tid; i < 128 * KP128 / 8; i += 256) {   // W blob copy, ONCE
        ((uint4*)Whi)[i] = ((const uint4*)g_w1hi)[i];
        ((uint4*)Wlo)[i] = ((const uint4*)g_w1lo)[i];
    }

    for (int tile = blockIdx.x; tile < NT64; tile += gridDim.x) {
        int node0 = tile * 64;
        __syncthreads();   // W ready (iter0) / previous MMA done reading A

        for (int i = tid; i < 64 * 8; i += 256) {        // A cols 0..63 = feat
            int r = i >> 3, q = i & 7;
            int gn = node0 + r;
            uint4 vh = make_uint4(0,0,0,0), vl = vh;
            if (gn < N_NODES) {
                vh = ((const uint4*)(g_fhi + (size_t)gn * D_IN))[q];
                vl = ((const uint4*)(g_flo + (size_t)gn * D_IN))[q];
            }
            *(uint4*)&Ahi[r * KP128 + q * 8] = vh;
            *(uint4*)&Alo[r * KP128 + q * 8] = vl;
        }
        for (int i = tid; i < 64 * 16; i += 256) {       // A cols 64..127 = a1 fp16
            int r = i >> 4, q = i & 15;
            int gn = node0 + r;
            uint2 v = make_uint2(0, 0);
            if (gn < N_NODES)
                v = *(const uint2*)(g_a1f + (size_t)gn * D_IN + q * 4);
            uint2 oh, ol; h4_to_hilo(v, oh, ol);
            *(uint2*)&Ahi[r * KP128 + 64 + q * 4] = oh;
            *(uint2*)&Alo[r * KP128 + 64 + q * 4] = ol;
        }
        __syncthreads();

        float acc[1][8][4];
#pragma unroll
        for (int b = 0; b < 8; b++)
#pragma unroll
            for (int c = 0; c < 4; c++) acc[0][b][c] = 0.f;

#pragma unroll
        for (int ks = 0; ks < 8; ks++)
            mma_step<1, 8>(acc, Ahi, Alo, KP128, Whi, Wlo, KP128,
                           m0, n0, ks * 16, ks * 16, g, t);

        int r0 = node0 + m0 + g;
#pragma unroll
        for (int nf = 0; nf < 8; nf++) {
            int col = n0 + nf * 8 + t * 2;
            float2 bv = *(const float2*)&b1[col];
            if (r0 < N_NODES) {
                float v0 = sigmoidf_(acc[0][nf][0] + bv.x);
                float v1 = sigmoidf_(acc[0][nf][1] + bv.y);
                *(__half2*)&g_h1f[(size_t)r0 * D_H + col] = __floats2half2_rn(v0, v1);
            }
            if (r0 + 8 < N_NODES) {
                float v0 = sigmoidf_(acc[0][nf][2] + bv.x);
                float v1 = sigmoidf_(acc[0][nf][3] + bv.y);
                *(__half2*)&g_h1f[(size_t)(r0 + 8) * D_H + col] = __floats2half2_rn(v0, v1);
            }
        }
    }
}

// ============================================================================
// Fused L2 + MLP1 + MLP2 (M=64/blk, 2-occ).  h2 and h3 never leave smem.
// ============================================================================
#define F_SMEM ((2 * 64 * KP128 + 2 * 128 * KP128) * 2)
__global__ void __launch_bounds__(256, 2)
fused_l2_mlp_kernel(const float* __restrict__ b2, const float* __restrict__ bm1,
                    const float* __restrict__ bm2, float* __restrict__ out) {
    extern __shared__ unsigned char smraw[];
    __nv_bfloat16* Ahi = (__nv_bfloat16*)smraw;        // [64][KP128]
    __nv_bfloat16* Alo = Ahi + 64 * KP128;
    __nv_bfloat16* Whi = Alo + 64 * KP128;             // [128][KP128]
    __nv_bfloat16* Wlo = Whi + 128 * KP128;
    int tid = threadIdx.x;
    int node0 = blockIdx.x * 64;
    int w = tid >> 5, lane = tid & 31, g = lane >> 2, t = lane & 3;
    int m0 = (w & 3) * 16, n0 = (w >> 2) * 64;

    // ---------------- phase A: layer-2 GEMM ----------------
    float acc[1][8][4];
#pragma unroll
    for (int b = 0; b < 8; b++)
#pragma unroll
        for (int c = 0; c < 4; c++) acc[0][b][c] = 0.f;

    for (int kc = 0; kc < 2; kc++) {
        if (kc) __syncthreads();
        for (int i = tid; i < 128 * 16; i += 256) {    // W2 chunk rows
            int n = i >> 4, q = i & 15;
            *(uint4*)&Whi[n * KP128 + q * 8] =
                *(const uint4*)&g_w2hi[n * KP256 + kc * 128 + q * 8];
            *(uint4*)&Wlo[n * KP128 + q * 8] =
                *(const uint4*)&g_w2lo[n * KP256 + kc * 128 + q * 8];
        }
        const __half* src = kc ? g_a2f : g_h1f;        // both fp16 [node][128]
        for (int i = tid; i < 64 * 32; i += 256) {
            int r = i >> 5, q = i & 31;                // q = group of 4 dims
            int gn = node0 + r;
            uint2 v = make_uint2(0, 0);
            if (gn < N_NODES)
                v = *(const uint2*)(src + (size_t)gn * D_H + q * 4);
            uint2 oh, ol; h4_to_hilo(v, oh, ol);
            *(uint2*)&Ahi[r * KP128 + q * 4] = oh;
            *(uint2*)&Alo[r * KP128 + q * 4] = ol;
        }
        __syncthreads();
#pragma unroll
        for (int ks = 0; ks < 8; ks++)
            mma_step<1, 8>(acc, Ahi, Alo, KP128, Whi, Wlo, KP128,
                           m0, n0, ks * 16, ks * 16, g, t);
    }
    __syncthreads();     // all warps done reading A before overwriting with h2

    // epilogue A: h2 -> A buffer (sigmoid + split), rows are block-local
    {
        int rr = m0 + g;
#pragma unroll
        for (int nf = 0; nf < 8; nf++) {
            int col = n0 + nf * 8 + t * 2;
            float2 bv = *(const float2*)&b2[col];
            float v0 = sigmoidf_(acc[0][nf][0] + bv.x);
            float v1 = sigmoidf_(acc[0][nf][1] + bv.y);
            float v2 = sigmoidf_(acc[0][nf][2] + bv.x);
            float v3 = sigmoidf_(acc[0][nf][3] + bv.y);
            __nv_bfloat16 h0, l0, h1, l1; split2(v0, h0, l0); split2(v1, h1, l1);
            *(unsigned*)&Ahi[rr * KP128 + col] = pack_bf2(h0, h1);
            *(unsigned*)&Alo[rr * KP128 + col] = pack_bf2(l0, l1);
            split2(v2, h0, l0); split2(v3, h1, l1);
            *(unsigned*)&Ahi[(rr + 8) * KP128 + col] = pack_bf2(h0, h1);
            *(unsigned*)&Alo[(rr + 8) * KP128 + col] = pack_bf2(l0, l1);
        }
    }
    __syncthreads();

    // ---------------- phase B: MLP1 half + MLP2 partial, per nb -------------
    float acc2[1][5][4];
#pragma unroll
    for (int b = 0; b < 5; b++)
#pragma unroll
        for (int c = 0; c < 4; c++) acc2[0][b][c] = 0.f;

    for (int nb = 0; nb < 2; nb++) {
        if (nb) __syncthreads();
        {   // stage Wm1 half nb (blob copy)
            const uint4* srcH = (const uint4*)(g_m1hi + nb * 128 * KP128);
            const uint4* srcL = (const uint4*)(g_m1lo + nb * 128 * KP128);
            for (int i = tid; i < 128 * KP128 / 8; i += 256) {
                ((uint4*)Whi)[i] = srcH[i];
                ((uint4*)Wlo)[i] = srcL[i];
            }
        }
        __syncthreads();

        float acc1[1][8][4];
#pragma unroll
        for (int b = 0; b < 8; b++)
#pragma unroll
            for (int c = 0; c < 4; c++) acc1[0][b][c] = 0.f;

#pragma unroll
        for (int ks = 0; ks < 8; ks++)
            mma_step<1, 8>(acc1, Ahi, Alo, KP128, Whi, Wlo, KP128,
                           m0, n0, ks * 16, ks * 16, g, t);
        __syncthreads();     // done reading Wm1 half; W buffer reusable

        // epilogue B1: h3half = relu(acc1 + bm1) -> W buffer rows 0..63
        {
            int rr = m0 + g;
#pragma unroll
            for (int nf = 0; nf < 8; nf++) {
                int colL = n0 + nf * 8 + t * 2;          // local 0..127
                float2 bv = *(const float2*)&bm1[nb * 128 + colL];
                float v0 = fmaxf(acc1[0][nf][0] + bv.x, 0.f);
                float v1 = fmaxf(acc1[0][nf][1] + bv.y, 0.f);
                float v2 = fmaxf(acc1[0][nf][2] + bv.x, 0.f);
                float v3 = fmaxf(acc1[0][nf][3] + bv.y, 0.f);
                __nv_bfloat16 h0, l0, h1, l1; split2(v0, h0, l0); split2(v1, h1, l1);
                *(unsigned*)&Whi[rr * KP128 + colL] = pack_bf2(h0, h1);
                *(unsigned*)&Wlo[rr * KP128 + colL] = pack_bf2(l0, l1);
                split2(v2, h0, l0); split2(v3, h1, l1);
                *(unsigned*)&Whi[(rr + 8) * KP128 + colL] = pack_bf2(h0, h1);
                *(unsigned*)&Wlo[(rr + 8) * KP128 + colL] = pack_bf2(l0, l1);
            }
        }
        // stage Wm2 k-half nb into W rows 64..103
        for (int i = tid; i < 40 * 16; i += 256) {
            int n = i >> 4, q = i & 15;
            *(uint4*)&Whi[(64 + n) * KP128 + q * 8] =
                *(const uint4*)&g_m2hi[n * KP256 + nb * 128 + q * 8];
            *(uint4*)&Wlo[(64 + n) * KP128 + q * 8] =
                *(const uint4*)&g_m2lo[n * KP256 + nb * 128 + q * 8];
        }
        __syncthreads();

        // m2 partial: warps 0-3, A = h3half (W rows 0..63), B = Wm2 (W rows 64+)
        if (w < 4) {
            int m0b = w * 16;
#pragma unroll
            for (int ks = 0; ks < 8; ks++)
                mma_step<1, 5>(acc2, Whi, Wlo, KP128,
                               Whi + 64 * KP128, Wlo + 64 * KP128, KP128,
                               m0b, 0, ks * 16, ks * 16, g, t);
        }
    }

    // ---------------- final epilogue: out = acc2 + bm2 ----------------------
    if (w < 4) {
        int r0 = node0 + w * 16 + g;
#pragma unroll
        for (int nf = 0; nf < 5; nf++) {
            int col = nf * 8 + t * 2;
            float2 bv = *(const float2*)&bm2[col];
            if (r0 < N_NODES) {
                float2 o = make_float2(acc2[0][nf][0] + bv.x, acc2[0][nf][1] + bv.y);
                *(float2*)&out[(size_t)r0 * D_OUT + col] = o;
            }
            if (r0 + 8 < N_NODES) {
                float2 o = make_float2(acc2[0][nf][2] + bv.x, acc2[0][nf][3] + bv.y);
                *(float2*)&out[(size_t)(r0 + 8) * D_OUT + col] = o;
            }
        }
    }
}

// ---------------- launch -----------------------------------------------------
extern "C" void kernel_launch(void* const* d_in, const int* in_sizes, int n_in,
                              void* d_out, int out_size) {
    const float* feat = (const float*)d_in[0];
    const int*   ei   = (const int*)d_in[1];     // int32 (JAX x64 disabled)
    const float* W1   = (const float*)d_in[2];
    const float* b1   = (const float*)d_in[3];
    const float* W2   = (const float*)d_in[4];
    const float* b2   = (const float*)d_in[5];
    const float* Wm1  = (const float*)d_in[6];
    const float* bm1  = (const float*)d_in[7];
    const float* Wm2  = (const float*)d_in[8];
    const float* bm2  = (const float*)d_in[9];
    float* out = (float*)d_out;

    cudaFuncSetAttribute(l1_mma_kernel, cudaFuncAttributeMaxDynamicSharedMemorySize, L1_SMEM);
    cudaFuncSetAttribute(fused_l2_mlp_kernel, cudaFuncAttributeMaxDynamicSharedMemorySize, F_SMEM);

    // prep (zero degree + split feat + split weights) — one launch
    prep_kernel<<<(N_NODES * D_IN / 2 + 255) / 256, 256>>>(feat, W1, W2, Wm1, Wm2);

    // CSR build
    hist_kernel<<<(N_EDGES + 255) / 256, 256>>>(ei);
    scan1_kernel<<<NB_SCAN, 256>>>();
    scan23_kernel<<<NB_SCAN, 256>>>();
    fill_kernel<<<(N_EDGES + 255) / 256, 256>>>(ei);

    // layer 1
    gather1_kernel<<<(N_NODES * 32 + 255) / 256, 256>>>();
    l1_mma_kernel<<<L1_GRID, 256, L1_SMEM>>>(b1);

    // layer 2 + MLP (fused)
    gather2_kernel<<<(N_NODES * 32 + 255) / 256, 256>>>();
    fused_l2_mlp_kernel<<<NT64, 256, F_SMEM>>>(b2, bm1, bm2, out);
}

// round 16
// speedup vs baseline: 2.1761x; 1.5633x over previous
#include <cuda_runtime.h>
#include <cuda_fp16.h>

#define N_NODES 100000
#define N_EDGES 1600000
#define D_IN    64
#define D_H     128
#define D_M     256
#define D_OUT   40
#define NB_SCAN 391   // ceil(N_NODES/256)
#define KP128 136
#define KP256 264
#define NT128  ((N_NODES + 127) / 128)   // 782 node tiles
#define L1_GRID 296

// ---------------- device-global scratch --------------------------------------
__device__ int g_cnt_i[N_NODES];
__device__ int g_rs  [N_NODES];
__device__ int g_wr  [N_NODES];
__device__ int g_bsum[512];
__device__ int g_adj [N_EDGES];
__device__ __align__(16) __half g_f16[(size_t)N_NODES * D_IN];   // fp16 feat
__device__ __align__(16) __half g_h1f[(size_t)N_NODES * D_H];    // fp16 h1
__device__ __align__(16) __half g_a1f[(size_t)N_NODES * D_IN];   // fp16 mean_neigh(feat)
__device__ __align__(16) __half g_a2f[(size_t)N_NODES * D_H];    // fp16 mean_neigh(h1)
// fp16 weights, n-major, padded to smem tile layout (stride KP*)
__device__ __align__(16) __half g_w1h[128 * KP128];
__device__ __align__(16) __half g_w2h[128 * KP256];
__device__ __align__(16) __half g_m1h[256 * KP128];
__device__ __align__(16) __half g_m2h[ 40 * KP256];

// ---------------- helpers ----------------------------------------------------
__device__ __forceinline__ float sigmoidf_(float x) {
    return 1.0f / (1.0f + __expf(-x));
}

__device__ __forceinline__ void mma_f16(float c[4], const unsigned a[4],
                                        unsigned b0, unsigned b1) {
    asm volatile("mma.sync.aligned.m16n8k16.row.col.f32.f16.f16.f32 "
                 "{%0,%1,%2,%3}, {%4,%5,%6,%7}, {%8,%9}, {%0,%1,%2,%3};"
                 : "+f"(c[0]), "+f"(c[1]), "+f"(c[2]), "+f"(c[3])
                 : "r"(a[0]), "r"(a[1]), "r"(a[2]), "r"(a[3]), "r"(b0), "r"(b1));
}

// one k16 step of a (MF*16)x(NF*8) warp tile, fp16 operands
template<int MF, int NF>
__device__ __forceinline__ void mma_step(
    float (&acc)[MF][NF][4],
    const __half* __restrict__ A, int KPa,
    const __half* __restrict__ W, int KPw,
    int m0, int n0, int kbA, int kbW, int g, int t)
{
    unsigned a[MF][4];
#pragma unroll
    for (int mf = 0; mf < MF; mf++) {
        int r = m0 + mf * 16 + g;
        a[mf][0] = *(const unsigned*)&A[(r    ) * KPa + kbA     + t * 2];
        a[mf][1] = *(const unsigned*)&A[(r + 8) * KPa + kbA     + t * 2];
        a[mf][2] = *(const unsigned*)&A[(r    ) * KPa + kbA + 8 + t * 2];
        a[mf][3] = *(const unsigned*)&A[(r + 8) * KPa + kbA + 8 + t * 2];
    }
#pragma unroll
    for (int nf = 0; nf < NF; nf++) {
        int n = n0 + nf * 8 + g;
        unsigned b0 = *(const unsigned*)&W[n * KPw + kbW     + t * 2];
        unsigned b1 = *(const unsigned*)&W[n * KPw + kbW + 8 + t * 2];
#pragma unroll
        for (int mf = 0; mf < MF; mf++)
            mma_f16(acc[mf][nf], a[mf], b0, b1);
    }
}

// ---------------- prep: zero degree + convert feat + convert weights ---------
__global__ void prep_kernel(const float* __restrict__ feat,
                            const float* __restrict__ W1, const float* __restrict__ W2,
                            const float* __restrict__ Wm1, const float* __restrict__ Wm2) {
    unsigned i = blockIdx.x * blockDim.x + threadIdx.x;
    if (i < N_NODES) g_cnt_i[i] = 0;
    if (i < N_NODES * D_IN / 2) {
        float2 v = __ldg(((const float2*)feat) + i);
        *(__half2*)&g_f16[i * 2] = __floats2half2_rn(v.x, v.y);
    }
    if (i < 92160) {
        if (i < 16384) {                        // W1 [128k][128n]
            int k = i >> 7, n = i & 127;
            g_w1h[n * KP128 + k] = __float2half_rn(__ldg(&W1[i]));
        } else if (i < 49152) {                 // W2 [256k][128n]
            int j = i - 16384; int k = j >> 7, n = j & 127;
            g_w2h[n * KP256 + k] = __float2half_rn(__ldg(&W2[j]));
        } else if (i < 81920) {                 // Wm1 [128k][256n]
            int j = i - 49152; int k = j >> 8, n = j & 255;
            g_m1h[n * KP128 + k] = __float2half_rn(__ldg(&Wm1[j]));
        } else {                                // Wm2 [256k][40n]
            int j = i - 81920; int k = j / 40, n = j % 40;
            g_m2h[n * KP256 + k] = __float2half_rn(__ldg(&Wm2[j]));
        }
    }
}

// ---------------- CSR build --------------------------------------------------
__global__ void hist_kernel(const int* __restrict__ ei) {
    unsigned e = blockIdx.x * blockDim.x + threadIdx.x;
    if (e >= N_EDGES) return;
    int s = __ldg(&ei[e]);
    int d = __ldg(&ei[N_EDGES + e]);
    if ((unsigned)s >= (unsigned)N_NODES || (unsigned)d >= (unsigned)N_NODES) return;
    atomicAdd(&g_cnt_i[d], 1);
}
__global__ void scan1_kernel() {
    __shared__ int sm[256];
    int t = threadIdx.x, b = blockIdx.x;
    int i = b * 256 + t;
    int v = (i < N_NODES) ? g_cnt_i[i] : 0;
    sm[t] = v; __syncthreads();
    for (int off = 1; off < 256; off <<= 1) {
        int x = (t >= off) ? sm[t - off] : 0;
        __syncthreads(); sm[t] += x; __syncthreads();
    }
    if (i < N_NODES) g_rs[i] = sm[t] - v;
    if (t == 255) g_bsum[b] = sm[255];
}
__global__ void scan23_kernel() {           // per-block lookback + finalize
    __shared__ int red[256];
    int t = threadIdx.x, b = blockIdx.x;
    int partial = 0;
    for (int j = t; j < b; j += 256) partial += g_bsum[j];
    red[t] = partial; __syncthreads();
    for (int off = 128; off > 0; off >>= 1) {
        if (t < off) red[t] += red[t + off];
        __syncthreads();
    }
    int base = red[0];
    int i = b * 256 + t;
    if (i < N_NODES) {
        int v = g_rs[i] + base;
        g_rs[i] = v;
        g_wr[i] = v;
    }
}
__global__ void fill_kernel(const int* __restrict__ ei) {
    unsigned e = blockIdx.x * blockDim.x + threadIdx.x;
    if (e >= N_EDGES) return;
    int s = __ldg(&ei[e]);
    int d = __ldg(&ei[N_EDGES + e]);
    if ((unsigned)s >= (unsigned)N_NODES || (unsigned)d >= (unsigned)N_NODES) return;
    g_adj[atomicAdd(&g_wr[d], 1)] = s;
}

// ---------------- gather-reduce (warp per node), fp16 outputs ----------------
__global__ void gather1_kernel() {
    int warp = (blockIdx.x * blockDim.x + threadIdx.x) >> 5;
    int lane = threadIdx.x & 31;
    if (warp >= N_NODES) return;
    int deg = g_cnt_i[warp], start = g_rs[warp];
    float2 acc = make_float2(0.f, 0.f);
    for (int j = 0; j < deg; j++) {
        int s = __ldg(&g_adj[start + j]);
        __half2 v = *(const __half2*)(g_f16 + (size_t)s * D_IN + lane * 2);
        float2 f = __half22float2(v);
        acc.x += f.x; acc.y += f.y;
    }
    float rcp = 1.0f / fmaxf((float)deg, 1.0f);
    *(__half2*)&g_a1f[(size_t)warp * D_IN + lane * 2] =
        __floats2half2_rn(acc.x * rcp, acc.y * rcp);
}

__global__ void gather2_kernel() {
    int warp = (blockIdx.x * blockDim.x + threadIdx.x) >> 5;
    int lane = threadIdx.x & 31;
    if (warp >= N_NODES) return;
    int deg = g_cnt_i[warp], start = g_rs[warp];
    float4 acc = make_float4(0.f, 0.f, 0.f, 0.f);
    for (int j = 0; j < deg; j++) {
        int s = __ldg(&g_adj[start + j]);
        uint2 v = *(const uint2*)(g_h1f + (size_t)s * D_H + lane * 4);
        float2 a = __half22float2(*(__half2*)&v.x);
        float2 b = __half22float2(*(__half2*)&v.y);
        acc.x += a.x; acc.y += a.y; acc.z += b.x; acc.w += b.y;
    }
    float rcp = 1.0f / fmaxf((float)deg, 1.0f);
    uint2 o;
    *(__half2*)&o.x = __floats2half2_rn(acc.x * rcp, acc.y * rcp);
    *(__half2*)&o.y = __floats2half2_rn(acc.z * rcp, acc.w * rcp);
    *(uint2*)&g_a2f[(size_t)warp * D_H + lane * 4] = o;
}

// ============================================================================
// Layer-1 (persistent): h1 = sigmoid([feat | a1] @ W1 + b1)
// M=128/tile, N=128, K=128, 2-occ, W1 staged once per block, all fp16.
// ============================================================================
#define L1_SMEM ((128 * KP128 + 128 * KP128) * 2)
__global__ void __launch_bounds__(256, 2)
l1_mma_kernel(const float* __restrict__ b1) {
    extern __shared__ unsigned char smraw[];
    __half* As = (__half*)smraw;              // [128][KP128]
    __half* Ws = As + 128 * KP128;            // [128][KP128]
    int tid = threadIdx.x;
    int w = tid >> 5, lane = tid & 31, g = lane >> 2, t = lane & 3;
    int m0 = (w & 3) * 32, n0 = (w >> 2) * 64;

    for (int i = tid; i < 128 * KP128 / 8; i += 256)     // W1 blob copy, ONCE
        ((uint4*)Ws)[i] = ((const uint4*)g_w1h)[i];

    for (int tile = blockIdx.x; tile < NT128; tile += gridDim.x) {
        int node0 = tile * 128;
        __syncthreads();   // W ready (iter0) / previous MMA done reading A

        for (int i = tid; i < 128 * 8; i += 256) {       // A cols 0..63 = feat
            int r = i >> 3, q = i & 7;
            int gn = node0 + r;
            uint4 v = make_uint4(0,0,0,0);
            if (gn < N_NODES) v = ((const uint4*)(g_f16 + (size_t)gn * D_IN))[q];
            *(uint4*)&As[r * KP128 + q * 8] = v;
        }
        for (int i = tid; i < 128 * 8; i += 256) {       // A cols 64..127 = a1
            int r = i >> 3, q = i & 7;
            int gn = node0 + r;
            uint4 v = make_uint4(0,0,0,0);
            if (gn < N_NODES) v = ((const uint4*)(g_a1f + (size_t)gn * D_IN))[q];
            *(uint4*)&As[r * KP128 + 64 + q * 8] = v;
        }
        __syncthreads();

        float acc[2][8][4];
#pragma unroll
        for (int a = 0; a < 2; a++)
#pragma unroll
            for (int b = 0; b < 8; b++)
#pragma unroll
                for (int c = 0; c < 4; c++) acc[a][b][c] = 0.f;

#pragma unroll
        for (int ks = 0; ks < 8; ks++)
            mma_step<2, 8>(acc, As, KP128, Ws, KP128,
                           m0, n0, ks * 16, ks * 16, g, t);

#pragma unroll
        for (int mf = 0; mf < 2; mf++) {
            int r0 = node0 + m0 + mf * 16 + g;
#pragma unroll
            for (int nf = 0; nf < 8; nf++) {
                int col = n0 + nf * 8 + t * 2;
                float2 bv = *(const float2*)&b1[col];
                if (r0 < N_NODES) {
                    float v0 = sigmoidf_(acc[mf][nf][0] + bv.x);
                    float v1 = sigmoidf_(acc[mf][nf][1] + bv.y);
                    *(__half2*)&g_h1f[(size_t)r0 * D_H + col] = __floats2half2_rn(v0, v1);
                }
                if (r0 + 8 < N_NODES) {
                    float v0 = sigmoidf_(acc[mf][nf][2] + bv.x);
                    float v1 = sigmoidf_(acc[mf][nf][3] + bv.y);
                    *(__half2*)&g_h1f[(size_t)(r0 + 8) * D_H + col] = __floats2half2_rn(v0, v1);
                }
            }
        }
    }
}

// ============================================================================
// Fused L2 + MLP1 + MLP2 (M=128/blk, 2-occ, all fp16).  h2/h3 stay in smem.
//   phase A: h2 = sigmoid([h1 | a2] @ W2 + b2) -> A buffer
//   per n-half nb: h3half = relu(h2 @ Wm1half + bm1) -> W buffer (128 rows)
//                  acc2 += h3half @ Wm2half (staged in W2b)
//   out = acc2 + bm2
// ============================================================================
#define F_SMEM ((128 * KP128 + 128 * KP128 + 40 * KP128) * 2)
__global__ void __launch_bounds__(256, 2)
fused_l2_mlp_kernel(const float* __restrict__ b2, const float* __restrict__ bm1,
                    const float* __restrict__ bm2, float* __restrict__ out) {
    extern __shared__ unsigned char smraw[];
    __half* As  = (__half*)smraw;             // [128][KP128]
    __half* Ws  = As + 128 * KP128;           // [128][KP128]
    __half* W2b = Ws + 128 * KP128;           // [40][KP128]
    int tid = threadIdx.x;
    int node0 = blockIdx.x * 128;
    int w = tid >> 5, lane = tid & 31, g = lane >> 2, t = lane & 3;
    int m0 = (w & 3) * 32, n0 = (w >> 2) * 64;

    // ---------------- phase A: layer-2 GEMM ----------------
    float acc[2][8][4];
#pragma unroll
    for (int a = 0; a < 2; a++)
#pragma unroll
        for (int b = 0; b < 8; b++)
#pragma unroll
            for (int c = 0; c < 4; c++) acc[a][b][c] = 0.f;

    for (int kc = 0; kc < 2; kc++) {
        if (kc) __syncthreads();
        for (int i = tid; i < 128 * 16; i += 256) {    // W2 chunk rows
            int n = i >> 4, q = i & 15;
            *(uint4*)&Ws[n * KP128 + q * 8] =
                *(const uint4*)&g_w2h[n * KP256 + kc * 128 + q * 8];
        }
        const __half* src = kc ? g_a2f : g_h1f;        // fp16 [node][128]
        for (int i = tid; i < 128 * 16; i += 256) {
            int r = i >> 4, q = i & 15;
            int gn = node0 + r;
            uint4 v = make_uint4(0,0,0,0);
            if (gn < N_NODES) v = ((const uint4*)(src + (size_t)gn * D_H))[q];
            *(uint4*)&As[r * KP128 + q * 8] = v;
        }
        __syncthreads();
#pragma unroll
        for (int ks = 0; ks < 8; ks++)
            mma_step<2, 8>(acc, As, KP128, Ws, KP128,
                           m0, n0, ks * 16, ks * 16, g, t);
    }
    __syncthreads();     // all warps done reading A before overwriting with h2

    // epilogue A: h2 -> A buffer (fp16), rows block-local
#pragma unroll
    for (int mf = 0; mf < 2; mf++) {
        int rr = m0 + mf * 16 + g;
#pragma unroll
        for (int nf = 0; nf < 8; nf++) {
            int col = n0 + nf * 8 + t * 2;
            float2 bv = *(const float2*)&b2[col];
            *(__half2*)&As[rr * KP128 + col] =
                __floats2half2_rn(sigmoidf_(acc[mf][nf][0] + bv.x),
                                  sigmoidf_(acc[mf][nf][1] + bv.y));
            *(__half2*)&As[(rr + 8) * KP128 + col] =
                __floats2half2_rn(sigmoidf_(acc[mf][nf][2] + bv.x),
                                  sigmoidf_(acc[mf][nf][3] + bv.y));
        }
    }
    __syncthreads();

    // ---------------- phase B: MLP1 half + MLP2 partial, per nb -------------
    float acc2[1][5][4];
#pragma unroll
    for (int b = 0; b < 5; b++)
#pragma unroll
        for (int c = 0; c < 4; c++) acc2[0][b][c] = 0.f;

    for (int nb = 0; nb < 2; nb++) {
        if (nb) __syncthreads();   // m2 MMA of nb=0 done reading Ws
        {   // stage Wm1 half nb (blob copy)
            const uint4* srcW = (const uint4*)(g_m1h + nb * 128 * KP128);
            for (int i = tid; i < 128 * KP128 / 8; i += 256)
                ((uint4*)Ws)[i] = srcW[i];
        }
        // stage Wm2 k-half nb into W2b (separate buffer; no conflict)
        for (int i = tid; i < 40 * 16; i += 256) {
            int n = i >> 4, q = i & 15;
            *(uint4*)&W2b[n * KP128 + q * 8] =
                *(const uint4*)&g_m2h[n * KP256 + nb * 128 + q * 8];
        }
        __syncthreads();

        float acc1[2][8][4];
#pragma unroll
        for (int a = 0; a < 2; a++)
#pragma unroll
            for (int b = 0; b < 8; b++)
#pragma unroll
                for (int c = 0; c < 4; c++) acc1[a][b][c] = 0.f;

#pragma unroll
        for (int ks = 0; ks < 8; ks++)
            mma_step<2, 8>(acc1, As, KP128, Ws, KP128,
                           m0, n0, ks * 16, ks * 16, g, t);
        __syncthreads();     // done reading Wm1 half; W buffer reusable

        // epilogue B1: h3half = relu(acc1 + bm1) -> W buffer (fp16, 128 rows)
#pragma unroll
        for (int mf = 0; mf < 2; mf++) {
            int rr = m0 + mf * 16 + g;
#pragma unroll
            for (int nf = 0; nf < 8; nf++) {
                int colL = n0 + nf * 8 + t * 2;          // local 0..127
                float2 bv = *(const float2*)&bm1[nb * 128 + colL];
                *(__half2*)&Ws[rr * KP128 + colL] =
                    __floats2half2_rn(fmaxf(acc1[mf][nf][0] + bv.x, 0.f),
                                      fmaxf(acc1[mf][nf][1] + bv.y, 0.f));
                *(__half2*)&Ws[(rr + 8) * KP128 + colL] =
                    __floats2half2_rn(fmaxf(acc1[mf][nf][2] + bv.x, 0.f),
                                      fmaxf(acc1[mf][nf][3] + bv.y, 0.f));
            }
        }
        __syncthreads();

        // m2 partial: all 8 warps, A = h3half (Ws), B = Wm2 half (W2b)
        {
            int m0b = w * 16;
#pragma unroll
            for (int ks = 0; ks < 8; ks++)
                mma_step<1, 5>(acc2, Ws, KP128, W2b, KP128,
                               m0b, 0, ks * 16, ks * 16, g, t);
        }
    }

    // ---------------- final epilogue: out = acc2 + bm2 ----------------------
    {
        int r0 = node0 + w * 16 + g;
#pragma unroll
        for (int nf = 0; nf < 5; nf++) {
            int col = nf * 8 + t * 2;
            float2 bv = *(const float2*)&bm2[col];
            if (r0 < N_NODES) {
                float2 o = make_float2(acc2[0][nf][0] + bv.x, acc2[0][nf][1] + bv.y);
                *(float2*)&out[(size_t)r0 * D_OUT + col] = o;
            }
            if (r0 + 8 < N_NODES) {
                float2 o = make_float2(acc2[0][nf][2] + bv.x, acc2[0][nf][3] + bv.y);
                *(float2*)&out[(size_t)(r0 + 8) * D_OUT + col] = o;
            }
        }
    }
}

// ---------------- launch -----------------------------------------------------
extern "C" void kernel_launch(void* const* d_in, const int* in_sizes, int n_in,
                              void* d_out, int out_size) {
    const float* feat = (const float*)d_in[0];
    const int*   ei   = (const int*)d_in[1];     // int32 (JAX x64 disabled)
    const float* W1   = (const float*)d_in[2];
    const float* b1   = (const float*)d_in[3];
    const float* W2   = (const float*)d_in[4];
    const float* b2   = (const float*)d_in[5];
    const float* Wm1  = (const float*)d_in[6];
    const float* bm1  = (const float*)d_in[7];
    const float* Wm2  = (const float*)d_in[8];
    const float* bm2  = (const float*)d_in[9];
    float* out = (float*)d_out;

    cudaFuncSetAttribute(l1_mma_kernel, cudaFuncAttributeMaxDynamicSharedMemorySize, L1_SMEM);
    cudaFuncSetAttribute(fused_l2_mlp_kernel, cudaFuncAttributeMaxDynamicSharedMemorySize, F_SMEM);

    // prep (zero degree + convert feat + convert weights) — one launch
    prep_kernel<<<(N_NODES * D_IN / 2 + 255) / 256, 256>>>(feat, W1, W2, Wm1, Wm2);

    // CSR build
    hist_kernel<<<(N_EDGES + 255) / 256, 256>>>(ei);
    scan1_kernel<<<NB_SCAN, 256>>>();
    scan23_kernel<<<NB_SCAN, 256>>>();
    fill_kernel<<<(N_EDGES + 255) / 256, 256>>>(ei);

    // layer 1
    gather1_kernel<<<(N_NODES * 32 + 255) / 256, 256>>>();
    l1_mma_kernel<<<L1_GRID, 256, L1_SMEM>>>(b1);

    // layer 2 + MLP (fused)
    gather2_kernel<<<(N_NODES * 32 + 255) / 256, 256>>>();
    fused_l2_mlp_kernel<<<NT128, 256, F_SMEM>>>(b2, bm1, bm2, out);
}